// round 1
// baseline (speedup 1.0000x reference)
#include <cuda_runtime.h>
#include <math.h>

// Problem dims
#define BB   2
#define NN   256
#define ND   128
#define ED   256
#define HIDD 256
#define NH   8
#define DH   32
#define LN_EPS 1e-5f

// ---------------- device scratch (no allocations allowed) ----------------
__device__ float g_h   [BB*NN*HIDD];     // node projection (residual)
__device__ float g_q   [BB*NN*HIDD];
__device__ float g_k   [BB*NN*HIDD];
__device__ float g_v   [BB*NN*HIDD];
__device__ float g_scores[BB*NH*NN*NN];  // QK^T/sqrt(D), then attn after softmax
__device__ float g_eattn [BB*NH*NN*NN];  // edge attention bias
__device__ float g_amean [BB*NN*NN];     // mean attention over heads
__device__ float g_ao  [BB*NN*HIDD];     // attention output (head-merged)
__device__ float g_tmp [BB*NN*HIDD];     // attn_out @ Wo + bo
__device__ float g_P   [BB*NN*ED];       // h_out @ Weo

// ---------------- reductions ----------------
__device__ __forceinline__ float warpSum(float v) {
    #pragma unroll
    for (int o = 16; o; o >>= 1) v += __shfl_xor_sync(0xffffffffu, v, o);
    return v;
}
__device__ __forceinline__ float warpMax(float v) {
    #pragma unroll
    for (int o = 16; o; o >>= 1) v = fmaxf(v, __shfl_xor_sync(0xffffffffu, v, o));
    return v;
}
// block of 256 threads; red must have >= 8 floats of shared
__device__ __forceinline__ float blockSum256(float v, float* red) {
    v = warpSum(v);
    if ((threadIdx.x & 31) == 0) red[threadIdx.x >> 5] = v;
    __syncthreads();
    float s = red[0];
    #pragma unroll
    for (int q = 1; q < 8; q++) s += red[q];
    __syncthreads();
    return s;
}
__device__ __forceinline__ float blockMax256(float v, float* red) {
    v = warpMax(v);
    if ((threadIdx.x & 31) == 0) red[threadIdx.x >> 5] = v;
    __syncthreads();
    float s = red[0];
    #pragma unroll
    for (int q = 1; q < 8; q++) s = fmaxf(s, red[q]);
    __syncthreads();
    return s;
}

// ---------------- generic small GEMM: C[M,Nc] = A[M,K] @ W[K,Nc] (+bias) ----------------
// 64x64 tile, BK=16, 256 threads, 4x4 micro-tile. M,Nc multiples of 64; K multiple of 16.
__global__ __launch_bounds__(256)
void gemm_bias_kernel(const float* __restrict__ A, const float* __restrict__ W,
                      const float* __restrict__ bias, float* __restrict__ C,
                      int M, int Nc, int K)
{
    __shared__ float As[16][65];   // transposed: As[k][m]
    __shared__ float Ws[16][64];
    int tid = threadIdx.x;
    int r0 = blockIdx.y * 64;
    int c0 = blockIdx.x * 64;
    int tx = tid & 15, ty = tid >> 4;
    float acc[4][4] = {};

    for (int kc = 0; kc < K; kc += 16) {
        {   // A tile 64 rows x 16 k, vectorized, stored transposed
            int r = tid >> 2, c4 = tid & 3;
            float4 v = *(const float4*)(A + (size_t)(r0 + r) * K + kc + c4 * 4);
            As[c4*4+0][r] = v.x; As[c4*4+1][r] = v.y;
            As[c4*4+2][r] = v.z; As[c4*4+3][r] = v.w;
        }
        {   // W tile 16 k x 64 cols
            int r = tid >> 4, c4 = tid & 15;
            float4 v = *(const float4*)(W + (size_t)(kc + r) * Nc + c0 + c4 * 4);
            *(float4*)(&Ws[r][c4*4]) = v;
        }
        __syncthreads();
        #pragma unroll
        for (int k = 0; k < 16; k++) {
            float a[4];
            #pragma unroll
            for (int i = 0; i < 4; i++) a[i] = As[k][ty*4+i];
            float4 bv = *(float4*)(&Ws[k][tx*4]);
            float b[4] = {bv.x, bv.y, bv.z, bv.w};
            #pragma unroll
            for (int i = 0; i < 4; i++)
                #pragma unroll
                for (int j = 0; j < 4; j++) acc[i][j] = fmaf(a[i], b[j], acc[i][j]);
        }
        __syncthreads();
    }
    #pragma unroll
    for (int i = 0; i < 4; i++)
        #pragma unroll
        for (int j = 0; j < 4; j++) {
            int c = c0 + tx*4 + j;
            float v = acc[i][j];
            if (bias) v += bias[c];
            C[(size_t)(r0 + ty*4 + i) * Nc + c] = v;
        }
}

// ---------------- scores = Q K^T / sqrt(D) ----------------
__global__ __launch_bounds__(256)
void scores_kernel()
{
    __shared__ float qrow[DH];
    int bid = blockIdx.x;                 // (b*NH + h)*NN + n
    int n = bid & 255, h = (bid >> 8) & 7, b = bid >> 11;
    int tid = threadIdx.x;
    if (tid < DH) qrow[tid] = g_q[(size_t)(b*NN + n)*HIDD + h*DH + tid];
    __syncthreads();
    const float* kr = g_k + (size_t)(b*NN + tid)*HIDD + h*DH;
    float s = 0.f;
    #pragma unroll
    for (int d = 0; d < DH; d++) s += qrow[d] * kr[d];
    g_scores[(((size_t)(b*NH + h)*NN + n)*NN) + tid] = s * 0.17677669529663687f; // 1/sqrt(32)
}

// ---------------- fused edge projection + gate + per-head reduction ----------------
// For 32 rows of E [131072,256]: P = E@Wep+bep, G = sigmoid(E@Weg+beg),
// edge_attn[b,h,n,m] = sum_d P[h*32+d]*G[h*32+d].  Never materializes P/G to HBM.
__global__ __launch_bounds__(256)
void edge_attn_kernel(const float* __restrict__ E,
                      const float* __restrict__ Wep, const float* __restrict__ bep,
                      const float* __restrict__ Weg, const float* __restrict__ beg)
{
    extern __shared__ float sm[];
    float* As = sm;             // [32][33] transposed A tile
    float* Bs = sm + 32*33;     // [32][512] concat (Wep|Weg) tile
    int tid = threadIdx.x;
    int i0 = blockIdx.x * 32;
    int rg = tid >> 6;          // 0..3  -> rows rg*8..rg*8+7
    int cg = tid & 63;          // 0..63 -> cols cg*8..cg*8+7 of 512
    float acc[8][8] = {};

    for (int kc = 0; kc < 256; kc += 32) {
        {   // A tile 32 rows x 32 k
            int r = tid >> 3, c4 = tid & 7;
            float4 v = *(const float4*)(E + (size_t)(i0 + r)*256 + kc + c4*4);
            As[(c4*4+0)*33 + r] = v.x;
            As[(c4*4+1)*33 + r] = v.y;
            As[(c4*4+2)*33 + r] = v.z;
            As[(c4*4+3)*33 + r] = v.w;
        }
        {   // B tile 32 k x 512 cols (first 256 Wep, next 256 Weg)
            #pragma unroll
            for (int j = tid; j < 32*128; j += 256) {
                int kk = j >> 7, c4 = j & 127;
                float4 v;
                if (c4 < 64) v = *(const float4*)(Wep + (size_t)(kc + kk)*256 + c4*4);
                else         v = *(const float4*)(Weg + (size_t)(kc + kk)*256 + (c4-64)*4);
                *(float4*)(Bs + kk*512 + c4*4) = v;
            }
        }
        __syncthreads();
        #pragma unroll
        for (int kk = 0; kk < 32; kk++) {
            float a[8];
            #pragma unroll
            for (int i = 0; i < 8; i++) a[i] = As[kk*33 + rg*8 + i];
            float4 b0 = *(float4*)(Bs + kk*512 + cg*8);
            float4 b1 = *(float4*)(Bs + kk*512 + cg*8 + 4);
            float b[8] = {b0.x,b0.y,b0.z,b0.w,b1.x,b1.y,b1.z,b1.w};
            #pragma unroll
            for (int i = 0; i < 8; i++)
                #pragma unroll
                for (int j = 0; j < 8; j++) acc[i][j] = fmaf(a[i], b[j], acc[i][j]);
        }
        __syncthreads();
    }

    // epilogue: bias + sigmoid gate, staged to smem (reusing Bs)
    float* Pact = Bs;            // [32][256]
    float* Gact = Bs + 32*256;   // [32][256]
    if (cg < 32) {
        #pragma unroll
        for (int i = 0; i < 8; i++) {
            int r = rg*8 + i;
            #pragma unroll
            for (int j = 0; j < 8; j++) {
                int c = cg*8 + j;
                Pact[r*256 + c] = acc[i][j] + bep[c];
            }
        }
    } else {
        #pragma unroll
        for (int i = 0; i < 8; i++) {
            int r = rg*8 + i;
            #pragma unroll
            for (int j = 0; j < 8; j++) {
                int c = (cg - 32)*8 + j;
                float g = acc[i][j] + beg[c];
                Gact[r*256 + c] = 1.f / (1.f + __expf(-g));
            }
        }
    }
    __syncthreads();

    // per-head reduction: 32 rows x 8 heads = 256 outputs, one per thread
    {
        int r = tid >> 3, hh = tid & 7;
        int base = r*256 + hh*32;
        float s = 0.f;
        #pragma unroll
        for (int d = 0; d < 32; d++) {
            int dp = (d + tid) & 31;   // phase to dodge bank conflicts
            s += Pact[base + dp] * Gact[base + dp];
        }
        int i = i0 + r;
        int m = i & 255, n = (i >> 8) & 255, b = i >> 16;
        g_eattn[(((size_t)(b*NH + hh)*NN + n)*NN) + m] = s;
    }
}

// ---------------- masked softmax (in-place into g_scores) ----------------
__global__ __launch_bounds__(256)
void softmax_kernel(const int* __restrict__ adj)
{
    __shared__ float red[8];
    int bid = blockIdx.x;                 // (b*NH + h)*NN + n
    int n = bid & 255, h = (bid >> 8) & 7, b = bid >> 11;
    int tid = threadIdx.x;
    size_t idx = (((size_t)(b*NH + h)*NN + n)*NN) + tid;
    float v = g_scores[idx] + g_eattn[idx];
    if (adj[(size_t)(b*NN + n)*NN + tid] == 0) v = -1e9f;
    float mx = blockMax256(v, red);
    float e = __expf(v - mx);
    float sum = blockSum256(e, red);
    g_scores[idx] = e / sum;
}

// ---------------- attn mean over heads ----------------
__global__ __launch_bounds__(256)
void attn_mean_kernel()
{
    int j = blockIdx.x * 256 + threadIdx.x;  // 0..131071 -> (b, n*256+m)
    int b = j >> 16, nm = j & 65535;
    float s = 0.f;
    #pragma unroll
    for (int h = 0; h < NH; h++) s += g_scores[(((size_t)(b*NH + h)) << 16) + nm];
    g_amean[j] = s * 0.125f;
}

// ---------------- attn @ V (per b,h,n row) ----------------
__global__ __launch_bounds__(256)
void attn_v_kernel()
{
    __shared__ float arow[256];
    __shared__ float red[256];
    int bid = blockIdx.x;                 // (b*NH + h)*NN + n
    int n = bid & 255, h = (bid >> 8) & 7, b = bid >> 11;
    int tid = threadIdx.x;
    arow[tid] = g_scores[(((size_t)(b*NH + h)*NN + n)*NN) + tid];
    __syncthreads();
    int d = tid & 31, mg = tid >> 5;
    float s = 0.f;
    #pragma unroll 4
    for (int q = 0; q < 32; q++) {
        int mm = mg*32 + q;
        s += arow[mm] * g_v[(size_t)(b*NN + mm)*HIDD + h*DH + d];
    }
    red[tid] = s;
    __syncthreads();
    if (tid < 32) {
        float t = 0.f;
        #pragma unroll
        for (int q = 0; q < 8; q++) t += red[q*32 + tid];
        g_ao[(size_t)(b*NN + n)*HIDD + h*DH + tid] = t;
    }
}

// ---------------- h_out = LN(residual + o) ----------------
__global__ __launch_bounds__(256)
void ln_node_kernel(const float* __restrict__ g1, const float* __restrict__ b1,
                    float* __restrict__ out)
{
    __shared__ float red[8];
    int i = blockIdx.x, c = threadIdx.x;
    float x = g_h[(size_t)i*256 + c] + g_tmp[(size_t)i*256 + c];
    float mean = blockSum256(x, red) * (1.f/256.f);
    float dxm = x - mean;
    float var = blockSum256(dxm*dxm, red) * (1.f/256.f);
    out[(size_t)i*256 + c] = dxm * rsqrtf(var + LN_EPS) * g1[c] + b1[c];
}

// ---------------- edge_out = LN(E + 0.5*amean*(P_n + P_m) + beo) ----------------
// Uses the identity (amean * pair) @ Weo = amean * 0.5*(h_out[n]@Weo + h_out[m]@Weo)
__global__ __launch_bounds__(256)
void edge_out_kernel(const float* __restrict__ E, const float* __restrict__ beo,
                     const float* __restrict__ g2, const float* __restrict__ b2,
                     float* __restrict__ out)
{
    __shared__ float red[8];
    int i = blockIdx.x;                    // (b,n,m) flat, 0..131071
    int c = threadIdx.x;
    int m = i & 255, n = (i >> 8) & 255, b = i >> 16;
    float am = g_amean[i] * 0.5f;
    float x = E[(size_t)i*256 + c]
            + am * (g_P[(size_t)(b*NN + n)*256 + c] + g_P[(size_t)(b*NN + m)*256 + c])
            + beo[c];
    float mean = blockSum256(x, red) * (1.f/256.f);
    float dxm = x - mean;
    float var = blockSum256(dxm*dxm, red) * (1.f/256.f);
    out[(size_t)i*256 + c] = dxm * rsqrtf(var + LN_EPS) * g2[c] + b2[c];
}

// ---------------- launch ----------------
extern "C" void kernel_launch(void* const* d_in, const int* in_sizes, int n_in,
                              void* d_out, int out_size)
{
    const float* node = (const float*)d_in[0];
    const float* edge = (const float*)d_in[1];
    const int*   adj  = (const int*)  d_in[2];
    const float* Wn  = (const float*)d_in[3];  const float* bn  = (const float*)d_in[4];
    const float* Wq  = (const float*)d_in[5];  const float* bq  = (const float*)d_in[6];
    const float* Wk  = (const float*)d_in[7];  const float* bk  = (const float*)d_in[8];
    const float* Wv  = (const float*)d_in[9];  const float* bv  = (const float*)d_in[10];
    const float* Wep = (const float*)d_in[11]; const float* bep = (const float*)d_in[12];
    const float* Weg = (const float*)d_in[13]; const float* beg = (const float*)d_in[14];
    const float* Wo  = (const float*)d_in[15]; const float* bo  = (const float*)d_in[16];
    const float* Weo = (const float*)d_in[17]; const float* beo = (const float*)d_in[18];
    const float* g1  = (const float*)d_in[19]; const float* b1  = (const float*)d_in[20];
    const float* g2  = (const float*)d_in[21]; const float* b2  = (const float*)d_in[22];

    float* out   = (float*)d_out;
    float* h_out = out;                       // [B,N,HID]
    float* e_out = out + (size_t)BB*NN*HIDD;  // [B,N,N,ED]

    // resolve scratch symbol addresses (host API, not stream-captured)
    float *ph, *pq, *pk, *pv, *pao, *ptmp, *pP;
    cudaGetSymbolAddress((void**)&ph,   g_h);
    cudaGetSymbolAddress((void**)&pq,   g_q);
    cudaGetSymbolAddress((void**)&pk,   g_k);
    cudaGetSymbolAddress((void**)&pv,   g_v);
    cudaGetSymbolAddress((void**)&pao,  g_ao);
    cudaGetSymbolAddress((void**)&ptmp, g_tmp);
    cudaGetSymbolAddress((void**)&pP,   g_P);

    const int EDGE_SMEM = (32*33 + 32*512) * 4;   // 69760 B
    cudaFuncSetAttribute(edge_attn_kernel,
                         cudaFuncAttributeMaxDynamicSharedMemorySize, EDGE_SMEM);

    dim3 g64(ED/64, (BB*NN)/64);   // (4, 8)

    // node projection + QKV
    gemm_bias_kernel<<<g64, 256>>>(node, Wn, bn, ph, BB*NN, HIDD, ND);
    gemm_bias_kernel<<<g64, 256>>>(ph, Wq, bq, pq, BB*NN, HIDD, HIDD);
    gemm_bias_kernel<<<g64, 256>>>(ph, Wk, bk, pk, BB*NN, HIDD, HIDD);
    gemm_bias_kernel<<<g64, 256>>>(ph, Wv, bv, pv, BB*NN, HIDD, HIDD);

    // attention scores + fused edge bias
    scores_kernel<<<BB*NH*NN, 256>>>();
    edge_attn_kernel<<<(BB*NN*NN)/32, 256, EDGE_SMEM>>>(edge, Wep, bep, Weg, beg);

    // softmax + mean
    softmax_kernel<<<BB*NH*NN, 256>>>(adj);
    attn_mean_kernel<<<(BB*NN*NN)/256, 256>>>();

    // attention output + out-proj + LN
    attn_v_kernel<<<BB*NH*NN, 256>>>();
    gemm_bias_kernel<<<g64, 256>>>(pao, Wo, bo, ptmp, BB*NN, HIDD, HIDD);
    ln_node_kernel<<<BB*NN, 256>>>(g1, b1, h_out);

    // P = h_out @ Weo  (the factored edge-update GEMM), then fused edge output
    gemm_bias_kernel<<<g64, 256>>>(h_out, Weo, (const float*)nullptr, pP, BB*NN, ED, HIDD);
    edge_out_kernel<<<BB*NN*NN, 256>>>(edge, beo, g2, b2, e_out);
}

// round 3
// speedup vs baseline: 2.9962x; 2.9962x over previous
#include <cuda_runtime.h>
#include <math.h>

// Problem dims
#define BB   2
#define NN   256
#define ND   128
#define ED   256
#define HIDD 256
#define NH   8
#define DH   32
#define LN_EPS 1e-5f

// ---------------- device scratch ----------------
__device__ float g_h   [BB*NN*HIDD];
__device__ float g_q   [BB*NN*HIDD];
__device__ float g_k   [BB*NN*HIDD];
__device__ float g_v   [BB*NN*HIDD];
__device__ float g_scores[BB*NH*NN*NN];
__device__ float g_eattn [BB*NH*NN*NN];
__device__ float g_amean [BB*NN*NN];
__device__ float g_ao  [BB*NN*HIDD];
__device__ float g_tmp [BB*NN*HIDD];
__device__ float g_P   [BB*NN*ED];
__device__ unsigned g_Wc[256*512];     // tf32 bits of [Wep | Weg], layout [k][512]

// ---------------- helpers ----------------
__device__ __forceinline__ float warpSum(float v) {
    #pragma unroll
    for (int o = 16; o; o >>= 1) v += __shfl_xor_sync(0xffffffffu, v, o);
    return v;
}
__device__ __forceinline__ float warpMax(float v) {
    #pragma unroll
    for (int o = 16; o; o >>= 1) v = fmaxf(v, __shfl_xor_sync(0xffffffffu, v, o));
    return v;
}
__device__ __forceinline__ float blockSum256(float v, float* red) {
    v = warpSum(v);
    if ((threadIdx.x & 31) == 0) red[threadIdx.x >> 5] = v;
    __syncthreads();
    float s = red[0];
    #pragma unroll
    for (int q = 1; q < 8; q++) s += red[q];
    __syncthreads();
    return s;
}
__device__ __forceinline__ float blockMax256(float v, float* red) {
    v = warpMax(v);
    if ((threadIdx.x & 31) == 0) red[threadIdx.x >> 5] = v;
    __syncthreads();
    float s = red[0];
    #pragma unroll
    for (int q = 1; q < 8; q++) s = fmaxf(s, red[q]);
    __syncthreads();
    return s;
}

__device__ __forceinline__ unsigned f2tf32(float x) {
    unsigned r;
    asm("cvt.rna.tf32.f32 %0, %1;" : "=r"(r) : "f"(x));
    return r;
}
__device__ __forceinline__ void mma_tf32(float* d, const unsigned* a, unsigned b0, unsigned b1) {
    asm volatile("mma.sync.aligned.m16n8k8.row.col.f32.tf32.tf32.f32 "
        "{%0,%1,%2,%3}, {%4,%5,%6,%7}, {%8,%9}, {%0,%1,%2,%3};"
        : "+f"(d[0]), "+f"(d[1]), "+f"(d[2]), "+f"(d[3])
        : "r"(a[0]), "r"(a[1]), "r"(a[2]), "r"(a[3]), "r"(b0), "r"(b1));
}
__device__ __forceinline__ void cp_async16(void* smem, const void* gmem) {
    unsigned saddr = (unsigned)__cvta_generic_to_shared(smem);
    asm volatile("cp.async.cg.shared.global [%0], [%1], 16;" :: "r"(saddr), "l"(gmem));
}
#define CP_COMMIT() asm volatile("cp.async.commit_group;")
#define CP_WAIT0()  asm volatile("cp.async.wait_group 0;")

// ---------------- weight pre-convert to tf32 ----------------
__global__ __launch_bounds__(256)
void cvt_w_kernel(const float* __restrict__ Wep, const float* __restrict__ Weg)
{
    int j = blockIdx.x * 256 + threadIdx.x;     // 0..131071
    int k = j >> 9, c = j & 511;
    float v = (c < 256) ? Wep[k*256 + c] : Weg[k*256 + (c - 256)];
    g_Wc[j] = f2tf32(v);
}

// ---------------- edge projection + gate + head reduction (tf32 MMA) ----------------
#define SAE 36
#define SBE 520
#define EDGE_SMEM ((2*64*SAE + 2*32*SBE) * 4)   // 151552 bytes

__device__ __forceinline__ void edge_loadA(unsigned* As, const float* __restrict__ E,
                                           size_t i0, int kc, int tid)
{
    int r = tid >> 3, c4 = tid & 7;
    float4 v = *(const float4*)(E + (i0 + r)*256 + kc + c4*4);
    unsigned* dst = As + r*SAE + c4*4;
    dst[0] = f2tf32(v.x); dst[1] = f2tf32(v.y);
    dst[2] = f2tf32(v.z); dst[3] = f2tf32(v.w);
}
__device__ __forceinline__ void edge_loadB(unsigned* Bs, int kc, int tid)
{
    #pragma unroll
    for (int it = 0; it < 8; it++) {
        int j = tid + it*512;            // 0..4095 float4
        int kk = j >> 7, c4 = j & 127;
        cp_async16(Bs + kk*SBE + c4*4, g_Wc + (size_t)(kc + kk)*512 + c4*4);
    }
    CP_COMMIT();
}

__global__ __launch_bounds__(512, 1)
void edge_attn_mma_kernel(const float* __restrict__ E,
                          const float* __restrict__ bep, const float* __restrict__ beg)
{
    extern __shared__ float sm[];
    unsigned* As0 = (unsigned*)sm;
    unsigned* As1 = As0 + 64*SAE;
    unsigned* Bs0 = As0 + 2*64*SAE;
    unsigned* Bs1 = Bs0 + 32*SBE;

    int tid  = threadIdx.x;
    int lane = tid & 31, w = tid >> 5;
    int g    = lane >> 2, tig = lane & 3;
    int rh   = w >> 3;                   // row half (0/1)
    int cw   = w & 7;                    // col warp
    int col0 = cw * 64;
    size_t i0 = (size_t)blockIdx.x * 64;

    float acc[2][8][4];
    #pragma unroll
    for (int mi = 0; mi < 2; mi++)
        #pragma unroll
        for (int nt = 0; nt < 8; nt++)
            #pragma unroll
            for (int q = 0; q < 4; q++) acc[mi][nt][q] = 0.f;

    edge_loadA(As0, E, i0, 0, tid);
    edge_loadB(Bs0, 0, tid);

    #pragma unroll 1
    for (int c = 0; c < 8; c++) {
        CP_WAIT0();
        __syncthreads();
        if (c < 7) {
            unsigned* An = (c & 1) ? As0 : As1;
            unsigned* Bn = (c & 1) ? Bs0 : Bs1;
            edge_loadA(An, E, i0, (c+1)*32, tid);
            edge_loadB(Bn, (c+1)*32, tid);
        }
        const unsigned* Au = (c & 1) ? As1 : As0;
        const unsigned* Bu = (c & 1) ? Bs1 : Bs0;
        #pragma unroll
        for (int ks = 0; ks < 4; ks++) {
            int k0 = ks * 8;
            unsigned a[2][4];
            #pragma unroll
            for (int mi = 0; mi < 2; mi++) {
                int r = rh*32 + mi*16 + g;
                a[mi][0] = Au[r*SAE + k0 + tig];
                a[mi][1] = Au[(r+8)*SAE + k0 + tig];
                a[mi][2] = Au[r*SAE + k0 + tig + 4];
                a[mi][3] = Au[(r+8)*SAE + k0 + tig + 4];
            }
            #pragma unroll
            for (int nt = 0; nt < 8; nt++) {
                int cb = col0 + nt*8 + g;
                unsigned b0 = Bu[(k0 + tig)*SBE + cb];
                unsigned b1 = Bu[(k0 + tig + 4)*SBE + cb];
                mma_tf32(acc[0][nt], a[0], b0, b1);
                mma_tf32(acc[1][nt], a[1], b0, b1);
            }
        }
        __syncthreads();
    }

    // epilogue: bias (+sigmoid for gate), stage to smem [64][264]
    float* Pact = sm;
    float* Gact = sm + 64*264;
    #pragma unroll
    for (int mi = 0; mi < 2; mi++)
        #pragma unroll
        for (int nt = 0; nt < 8; nt++) {
            int colg = col0 + nt*8 + tig*2;
            int r0 = rh*32 + mi*16 + g;
            if (cw < 4) {
                float b0v = bep[colg], b1v = bep[colg+1];
                Pact[r0*264 + colg]       = acc[mi][nt][0] + b0v;
                Pact[r0*264 + colg + 1]   = acc[mi][nt][1] + b1v;
                Pact[(r0+8)*264 + colg]   = acc[mi][nt][2] + b0v;
                Pact[(r0+8)*264 + colg+1] = acc[mi][nt][3] + b1v;
            } else {
                int cc = colg - 256;
                float b0v = beg[cc], b1v = beg[cc+1];
                float s0 = acc[mi][nt][0] + b0v, s1 = acc[mi][nt][1] + b1v;
                float s2 = acc[mi][nt][2] + b0v, s3 = acc[mi][nt][3] + b1v;
                Gact[r0*264 + cc]       = 1.f / (1.f + __expf(-s0));
                Gact[r0*264 + cc + 1]   = 1.f / (1.f + __expf(-s1));
                Gact[(r0+8)*264 + cc]   = 1.f / (1.f + __expf(-s2));
                Gact[(r0+8)*264 + cc+1] = 1.f / (1.f + __expf(-s3));
            }
        }
    __syncthreads();

    // per-head gated reduction: 64 rows x 8 heads = 512 outputs
    {
        int r = tid >> 3, h = tid & 7;
        int base = r*264 + h*32;
        float s = 0.f;
        #pragma unroll
        for (int d = 0; d < 32; d++) {
            int dp = (d + tid) & 31;
            s += Pact[base + dp] * Gact[base + dp];
        }
        size_t i = i0 + r;
        int m = (int)(i & 255), n = (int)((i >> 8) & 255), b = (int)(i >> 16);
        g_eattn[(((size_t)(b*NH + h)*NN + n)*NN) + m] = s;
    }
}

// ---------------- generic fp32 GEMM body: 32x64 tile, BK=32 ----------------
__device__ __forceinline__ void gemm_body(const float* __restrict__ A, const float* __restrict__ W,
                                          const float* __restrict__ bias, float* __restrict__ C,
                                          int M, int Nc, int K, int bx, int by)
{
    __shared__ float As[32][33];   // [k][r]
    __shared__ float Ws[32][64];
    int tid = threadIdx.x;
    int r0 = by * 32, c0 = bx * 64;
    int ty = tid >> 4, tx = tid & 15;   // rows ty*2..+1, cols tx*4..+3
    float acc[2][4] = {};

    for (int kc = 0; kc < K; kc += 32) {
        {
            int r = tid >> 3, c4 = tid & 7;
            float4 v = *(const float4*)(A + (size_t)(r0 + r)*K + kc + c4*4);
            As[c4*4+0][r] = v.x; As[c4*4+1][r] = v.y;
            As[c4*4+2][r] = v.z; As[c4*4+3][r] = v.w;
        }
        #pragma unroll
        for (int it = 0; it < 2; it++) {
            int j = tid + it*256;
            int rr = j >> 4, c4 = j & 15;
            *(float4*)(&Ws[rr][c4*4]) = *(const float4*)(W + (size_t)(kc + rr)*Nc + c0 + c4*4);
        }
        __syncthreads();
        #pragma unroll
        for (int k = 0; k < 32; k++) {
            float a0 = As[k][ty*2], a1 = As[k][ty*2+1];
            float4 bv = *(float4*)(&Ws[k][tx*4]);
            acc[0][0] = fmaf(a0, bv.x, acc[0][0]);
            acc[0][1] = fmaf(a0, bv.y, acc[0][1]);
            acc[0][2] = fmaf(a0, bv.z, acc[0][2]);
            acc[0][3] = fmaf(a0, bv.w, acc[0][3]);
            acc[1][0] = fmaf(a1, bv.x, acc[1][0]);
            acc[1][1] = fmaf(a1, bv.y, acc[1][1]);
            acc[1][2] = fmaf(a1, bv.z, acc[1][2]);
            acc[1][3] = fmaf(a1, bv.w, acc[1][3]);
        }
        __syncthreads();
    }
    #pragma unroll
    for (int i = 0; i < 2; i++)
        #pragma unroll
        for (int j = 0; j < 4; j++) {
            int cc = c0 + tx*4 + j;
            float v = acc[i][j];
            if (bias) v += bias[cc];
            C[(size_t)(r0 + ty*2 + i)*Nc + cc] = v;
        }
}

__global__ __launch_bounds__(256)
void gemm_one_kernel(const float* __restrict__ A, const float* __restrict__ W,
                     const float* __restrict__ bias, float* __restrict__ C,
                     int M, int Nc, int K)
{
    gemm_body(A, W, bias, C, M, Nc, K, blockIdx.x, blockIdx.y);
}

__global__ __launch_bounds__(256)
void gemm_qkv_kernel(const float* __restrict__ A,
                     const float* __restrict__ Wq, const float* __restrict__ bq,
                     const float* __restrict__ Wk, const float* __restrict__ bk,
                     const float* __restrict__ Wv, const float* __restrict__ bv,
                     float* __restrict__ oq, float* __restrict__ ok, float* __restrict__ ov)
{
    int z = blockIdx.z;
    const float* W = (z == 0) ? Wq : (z == 1) ? Wk : Wv;
    const float* bb = (z == 0) ? bq : (z == 1) ? bk : bv;
    float* C = (z == 0) ? oq : (z == 1) ? ok : ov;
    gemm_body(A, W, bb, C, 512, 256, 256, blockIdx.x, blockIdx.y);
}

// ---------------- scores = Q K^T / sqrt(D) ----------------
__global__ __launch_bounds__(256)
void scores_kernel()
{
    __shared__ float qrow[DH];
    int bid = blockIdx.x;
    int n = bid & 255, h = (bid >> 8) & 7, b = bid >> 11;
    int tid = threadIdx.x;
    if (tid < DH) qrow[tid] = g_q[(size_t)(b*NN + n)*HIDD + h*DH + tid];
    __syncthreads();
    const float* kr = g_k + (size_t)(b*NN + tid)*HIDD + h*DH;
    float s = 0.f;
    #pragma unroll
    for (int d = 0; d < DH; d++) s += qrow[d] * kr[d];
    g_scores[(((size_t)(b*NH + h)*NN + n)*NN) + tid] = s * 0.17677669529663687f;
}

// ---------------- masked softmax ----------------
__global__ __launch_bounds__(256)
void softmax_kernel(const int* __restrict__ adj)
{
    __shared__ float red[8];
    int bid = blockIdx.x;
    int n = bid & 255, h = (bid >> 8) & 7, b = bid >> 11;
    int tid = threadIdx.x;
    size_t idx = (((size_t)(b*NH + h)*NN + n)*NN) + tid;
    float v = g_scores[idx] + g_eattn[idx];
    if (adj[(size_t)(b*NN + n)*NN + tid] == 0) v = -1e9f;
    float mx = blockMax256(v, red);
    float e = __expf(v - mx);
    float sum = blockSum256(e, red);
    g_scores[idx] = e / sum;
}

// ---------------- attn mean over heads ----------------
__global__ __launch_bounds__(256)
void attn_mean_kernel()
{
    int j = blockIdx.x * 256 + threadIdx.x;
    int b = j >> 16, nm = j & 65535;
    float s = 0.f;
    #pragma unroll
    for (int h = 0; h < NH; h++) s += g_scores[(((size_t)(b*NH + h)) << 16) + nm];
    g_amean[j] = s * 0.125f;
}

// ---------------- attn @ V ----------------
__global__ __launch_bounds__(256)
void attn_v_kernel()
{
    __shared__ float arow[256];
    __shared__ float red[256];
    int bid = blockIdx.x;
    int n = bid & 255, h = (bid >> 8) & 7, b = bid >> 11;
    int tid = threadIdx.x;
    arow[tid] = g_scores[(((size_t)(b*NH + h)*NN + n)*NN) + tid];
    __syncthreads();
    int d = tid & 31, mg = tid >> 5;
    float s = 0.f;
    #pragma unroll 4
    for (int q = 0; q < 32; q++) {
        int mm = mg*32 + q;
        s += arow[mm] * g_v[(size_t)(b*NN + mm)*HIDD + h*DH + d];
    }
    red[tid] = s;
    __syncthreads();
    if (tid < 32) {
        float t = 0.f;
        #pragma unroll
        for (int q = 0; q < 8; q++) t += red[q*32 + tid];
        g_ao[(size_t)(b*NN + n)*HIDD + h*DH + tid] = t;
    }
}

// ---------------- h_out = LN(residual + o)  (warp per row) ----------------
__global__ __launch_bounds__(256)
void ln_node_kernel(const float* __restrict__ g1, const float* __restrict__ b1,
                    float* __restrict__ out)
{
    int row = blockIdx.x * 8 + (threadIdx.x >> 5);
    int lane = threadIdx.x & 31;
    const float* ha = g_h + (size_t)row*256;
    const float* ta = g_tmp + (size_t)row*256;
    float4 a0 = *(const float4*)(ha + lane*4);
    float4 t0 = *(const float4*)(ta + lane*4);
    float4 a1 = *(const float4*)(ha + 128 + lane*4);
    float4 t1 = *(const float4*)(ta + 128 + lane*4);
    float x[8] = {a0.x+t0.x, a0.y+t0.y, a0.z+t0.z, a0.w+t0.w,
                  a1.x+t1.x, a1.y+t1.y, a1.z+t1.z, a1.w+t1.w};
    float s = 0.f;
    #pragma unroll
    for (int j = 0; j < 8; j++) s += x[j];
    float mean = warpSum(s) * (1.f/256.f);
    float vs = 0.f;
    #pragma unroll
    for (int j = 0; j < 8; j++) { float d = x[j] - mean; vs += d*d; }
    float inv = rsqrtf(warpSum(vs) * (1.f/256.f) + LN_EPS);
    float* o = out + (size_t)row*256;
    #pragma unroll
    for (int j = 0; j < 8; j++) {
        int c = (j < 4) ? (lane*4 + j) : (128 + lane*4 + j - 4);
        o[c] = (x[j] - mean) * inv * g1[c] + b1[c];
    }
}

// ---------------- edge_out = LN(E + amean*0.5*(P_n + P_m) + beo)  (warp per row) ----------------
__global__ __launch_bounds__(256)
void edge_out_kernel(const float* __restrict__ E, const float* __restrict__ beo,
                     const float* __restrict__ g2, const float* __restrict__ b2,
                     float* __restrict__ out)
{
    size_t i = (size_t)blockIdx.x * 8 + (threadIdx.x >> 5);
    int lane = threadIdx.x & 31;
    int m = (int)(i & 255), n = (int)((i >> 8) & 255), b = (int)(i >> 16);
    float am = g_amean[i] * 0.5f;
    const float* Er = E + i*256;
    const float* Pn = g_P + (size_t)(b*NN + n)*256;
    const float* Pm = g_P + (size_t)(b*NN + m)*256;

    float x[8];
    #pragma unroll
    for (int half = 0; half < 2; half++) {
        int c = half*128 + lane*4;
        float4 e  = *(const float4*)(Er + c);
        float4 pn = *(const float4*)(Pn + c);
        float4 pm = *(const float4*)(Pm + c);
        float4 bo = *(const float4*)(beo + c);
        x[half*4+0] = e.x + am*(pn.x + pm.x) + bo.x;
        x[half*4+1] = e.y + am*(pn.y + pm.y) + bo.y;
        x[half*4+2] = e.z + am*(pn.z + pm.z) + bo.z;
        x[half*4+3] = e.w + am*(pn.w + pm.w) + bo.w;
    }
    float s = 0.f;
    #pragma unroll
    for (int j = 0; j < 8; j++) s += x[j];
    float mean = warpSum(s) * (1.f/256.f);
    float vs = 0.f;
    #pragma unroll
    for (int j = 0; j < 8; j++) { float d = x[j] - mean; vs += d*d; }
    float inv = rsqrtf(warpSum(vs) * (1.f/256.f) + LN_EPS);
    float* o = out + i*256;
    #pragma unroll
    for (int half = 0; half < 2; half++) {
        int c = half*128 + lane*4;
        float4 gg = *(const float4*)(g2 + c);
        float4 bb = *(const float4*)(b2 + c);
        float4 r;
        r.x = (x[half*4+0] - mean) * inv * gg.x + bb.x;
        r.y = (x[half*4+1] - mean) * inv * gg.y + bb.y;
        r.z = (x[half*4+2] - mean) * inv * gg.z + bb.z;
        r.w = (x[half*4+3] - mean) * inv * gg.w + bb.w;
        *(float4*)(o + c) = r;
    }
}

// ---------------- launch ----------------
extern "C" void kernel_launch(void* const* d_in, const int* in_sizes, int n_in,
                              void* d_out, int out_size)
{
    const float* node = (const float*)d_in[0];
    const float* edge = (const float*)d_in[1];
    const int*   adj  = (const int*)  d_in[2];
    const float* Wn  = (const float*)d_in[3];  const float* bn  = (const float*)d_in[4];
    const float* Wq  = (const float*)d_in[5];  const float* bq  = (const float*)d_in[6];
    const float* Wk  = (const float*)d_in[7];  const float* bk  = (const float*)d_in[8];
    const float* Wv  = (const float*)d_in[9];  const float* bv  = (const float*)d_in[10];
    const float* Wep = (const float*)d_in[11]; const float* bep = (const float*)d_in[12];
    const float* Weg = (const float*)d_in[13]; const float* beg = (const float*)d_in[14];
    const float* Wo  = (const float*)d_in[15]; const float* bo  = (const float*)d_in[16];
    const float* Weo = (const float*)d_in[17]; const float* beo = (const float*)d_in[18];
    const float* g1  = (const float*)d_in[19]; const float* b1  = (const float*)d_in[20];
    const float* g2  = (const float*)d_in[21]; const float* b2  = (const float*)d_in[22];

    float* out   = (float*)d_out;
    float* h_out = out;
    float* e_out = out + (size_t)BB*NN*HIDD;

    float *ph, *pq, *pk, *pv, *pao, *ptmp, *pP;
    cudaGetSymbolAddress((void**)&ph,   g_h);
    cudaGetSymbolAddress((void**)&pq,   g_q);
    cudaGetSymbolAddress((void**)&pk,   g_k);
    cudaGetSymbolAddress((void**)&pv,   g_v);
    cudaGetSymbolAddress((void**)&pao,  g_ao);
    cudaGetSymbolAddress((void**)&ptmp, g_tmp);
    cudaGetSymbolAddress((void**)&pP,   g_P);

    cudaFuncSetAttribute(edge_attn_mma_kernel,
                         cudaFuncAttributeMaxDynamicSharedMemorySize, EDGE_SMEM);

    // weight convert (independent) + node projection
    cvt_w_kernel<<<512, 256>>>(Wep, Weg);
    gemm_one_kernel<<<dim3(4, 16), 256>>>(node, Wn, bn, ph, 512, 256, 128);

    // QKV in one launch
    gemm_qkv_kernel<<<dim3(4, 16, 3), 256>>>(ph, Wq, bq, Wk, bk, Wv, bv, pq, pk, pv);

    // attention scores + fused edge bias (tensor cores)
    scores_kernel<<<BB*NH*NN, 256>>>();
    edge_attn_mma_kernel<<<(BB*NN*NN)/64, 512, EDGE_SMEM>>>(edge, bep, beg);

    // softmax + mean
    softmax_kernel<<<BB*NH*NN, 256>>>(adj);
    attn_mean_kernel<<<(BB*NN*NN)/256, 256>>>();

    // attention output + out-proj + LN
    attn_v_kernel<<<BB*NH*NN, 256>>>();
    gemm_one_kernel<<<dim3(4, 16), 256>>>(pao, Wo, bo, ptmp, 512, 256, 256);
    ln_node_kernel<<<(BB*NN)/8, 256>>>(g1, b1, h_out);

    // P = h_out @ Weo, then fused edge output LN
    gemm_one_kernel<<<dim3(4, 16), 256>>>(h_out, Weo, (const float*)nullptr, pP, 512, 256, 256);
    edge_out_kernel<<<(BB*NN*NN)/8, 256>>>(edge, beo, g2, b2, e_out);
}

// round 6
// speedup vs baseline: 3.8190x; 1.2746x over previous
#include <cuda_runtime.h>
#include <math.h>

// Problem dims
#define BB   2
#define NN   256
#define ND   128
#define ED   256
#define HIDD 256
#define NH   8
#define DH   32
#define LN_EPS 1e-5f

// ---------------- device scratch ----------------
__device__ float g_h   [BB*NN*HIDD];
__device__ float g_q   [BB*NN*HIDD];
__device__ float g_k   [BB*NN*HIDD];
__device__ float g_v   [BB*NN*HIDD];
__device__ float g_scores[BB*NH*NN*NN];   // attention probabilities
__device__ float g_eattn [BB*NH*NN*NN];
__device__ float g_amean [BB*NN*NN];
__device__ float g_ao  [BB*NN*HIDD];
__device__ float g_tmp [BB*NN*HIDD];
__device__ float g_P   [BB*NN*ED];
__device__ unsigned g_Wc[256*512];        // tf32 bits of [Wep | Weg], layout [k][512]

// ---------------- helpers ----------------
__device__ __forceinline__ float warpSum(float v) {
    #pragma unroll
    for (int o = 16; o; o >>= 1) v += __shfl_xor_sync(0xffffffffu, v, o);
    return v;
}

__device__ __forceinline__ unsigned f2tf32(float x) {
    unsigned r;
    asm("cvt.rna.tf32.f32 %0, %1;" : "=r"(r) : "f"(x));
    return r;
}
__device__ __forceinline__ void mma_tf32(float* d, const unsigned* a, unsigned b0, unsigned b1) {
    asm volatile("mma.sync.aligned.m16n8k8.row.col.f32.tf32.tf32.f32 "
        "{%0,%1,%2,%3}, {%4,%5,%6,%7}, {%8,%9}, {%0,%1,%2,%3};"
        : "+f"(d[0]), "+f"(d[1]), "+f"(d[2]), "+f"(d[3])
        : "r"(a[0]), "r"(a[1]), "r"(a[2]), "r"(a[3]), "r"(b0), "r"(b1));
}
__device__ __forceinline__ void cp_async16(void* smem, const void* gmem) {
    unsigned saddr = (unsigned)__cvta_generic_to_shared(smem);
    asm volatile("cp.async.cg.shared.global [%0], [%1], 16;" :: "r"(saddr), "l"(gmem));
}
#define CP_COMMIT() asm volatile("cp.async.commit_group;")
#define CP_WAIT0()  asm volatile("cp.async.wait_group 0;")

// ---------------- weight pre-convert to tf32 ----------------
__global__ __launch_bounds__(256)
void cvt_w_kernel(const float* __restrict__ Wep, const float* __restrict__ Weg)
{
    int j = blockIdx.x * 256 + threadIdx.x;
    int k = j >> 9, c = j & 511;
    float v = (c < 256) ? Wep[k*256 + c] : Weg[k*256 + (c - 256)];
    g_Wc[j] = f2tf32(v);
}

// ---------------- edge projection + gate + head reduction (tf32 MMA) ----------------
#define SAE 36
#define SBE 520
#define EDGE_SMEM ((2*64*SAE + 2*32*SBE) * 4)

__device__ __forceinline__ void edge_loadA(unsigned* As, const float* __restrict__ E,
                                           size_t i0, int kc, int tid)
{
    int r = tid >> 3, c4 = tid & 7;
    float4 v = *(const float4*)(E + (i0 + r)*256 + kc + c4*4);
    unsigned* dst = As + r*SAE + c4*4;
    dst[0] = f2tf32(v.x); dst[1] = f2tf32(v.y);
    dst[2] = f2tf32(v.z); dst[3] = f2tf32(v.w);
}
__device__ __forceinline__ void edge_loadB(unsigned* Bs, int kc, int tid)
{
    #pragma unroll
    for (int it = 0; it < 8; it++) {
        int j = tid + it*512;
        int kk = j >> 7, c4 = j & 127;
        cp_async16(Bs + kk*SBE + c4*4, g_Wc + (size_t)(kc + kk)*512 + c4*4);
    }
    CP_COMMIT();
}

__global__ __launch_bounds__(512, 1)
void edge_attn_mma_kernel(const float* __restrict__ E,
                          const float* __restrict__ bep, const float* __restrict__ beg)
{
    extern __shared__ float sm[];
    unsigned* As0 = (unsigned*)sm;
    unsigned* As1 = As0 + 64*SAE;
    unsigned* Bs0 = As0 + 2*64*SAE;
    unsigned* Bs1 = Bs0 + 32*SBE;

    int tid  = threadIdx.x;
    int lane = tid & 31, w = tid >> 5;
    int g    = lane >> 2, tig = lane & 3;
    int rh   = w >> 3;
    int cw   = w & 7;
    int col0 = cw * 64;
    size_t i0 = (size_t)blockIdx.x * 64;

    float acc[2][8][4];
    #pragma unroll
    for (int mi = 0; mi < 2; mi++)
        #pragma unroll
        for (int nt = 0; nt < 8; nt++)
            #pragma unroll
            for (int q = 0; q < 4; q++) acc[mi][nt][q] = 0.f;

    edge_loadA(As0, E, i0, 0, tid);
    edge_loadB(Bs0, 0, tid);

    #pragma unroll 1
    for (int c = 0; c < 8; c++) {
        CP_WAIT0();
        __syncthreads();
        if (c < 7) {
            unsigned* An = (c & 1) ? As0 : As1;
            unsigned* Bn = (c & 1) ? Bs0 : Bs1;
            edge_loadA(An, E, i0, (c+1)*32, tid);
            edge_loadB(Bn, (c+1)*32, tid);
        }
        const unsigned* Au = (c & 1) ? As1 : As0;
        const unsigned* Bu = (c & 1) ? Bs1 : Bs0;
        #pragma unroll
        for (int ks = 0; ks < 4; ks++) {
            int k0 = ks * 8;
            unsigned a[2][4];
            #pragma unroll
            for (int mi = 0; mi < 2; mi++) {
                int r = rh*32 + mi*16 + g;
                a[mi][0] = Au[r*SAE + k0 + tig];
                a[mi][1] = Au[(r+8)*SAE + k0 + tig];
                a[mi][2] = Au[r*SAE + k0 + tig + 4];
                a[mi][3] = Au[(r+8)*SAE + k0 + tig + 4];
            }
            #pragma unroll
            for (int nt = 0; nt < 8; nt++) {
                int cb = col0 + nt*8 + g;
                unsigned b0 = Bu[(k0 + tig)*SBE + cb];
                unsigned b1 = Bu[(k0 + tig + 4)*SBE + cb];
                mma_tf32(acc[0][nt], a[0], b0, b1);
                mma_tf32(acc[1][nt], a[1], b0, b1);
            }
        }
        __syncthreads();
    }

    float* Pact = sm;
    float* Gact = sm + 64*264;
    #pragma unroll
    for (int mi = 0; mi < 2; mi++)
        #pragma unroll
        for (int nt = 0; nt < 8; nt++) {
            int colg = col0 + nt*8 + tig*2;
            int r0 = rh*32 + mi*16 + g;
            if (cw < 4) {
                float b0v = bep[colg], b1v = bep[colg+1];
                Pact[r0*264 + colg]       = acc[mi][nt][0] + b0v;
                Pact[r0*264 + colg + 1]   = acc[mi][nt][1] + b1v;
                Pact[(r0+8)*264 + colg]   = acc[mi][nt][2] + b0v;
                Pact[(r0+8)*264 + colg+1] = acc[mi][nt][3] + b1v;
            } else {
                int cc = colg - 256;
                float b0v = beg[cc], b1v = beg[cc+1];
                float s0 = acc[mi][nt][0] + b0v, s1 = acc[mi][nt][1] + b1v;
                float s2 = acc[mi][nt][2] + b0v, s3 = acc[mi][nt][3] + b1v;
                Gact[r0*264 + cc]       = 1.f / (1.f + __expf(-s0));
                Gact[r0*264 + cc + 1]   = 1.f / (1.f + __expf(-s1));
                Gact[(r0+8)*264 + cc]   = 1.f / (1.f + __expf(-s2));
                Gact[(r0+8)*264 + cc+1] = 1.f / (1.f + __expf(-s3));
            }
        }
    __syncthreads();

    {
        int r = tid >> 3, h = tid & 7;
        int base = r*264 + h*32;
        float s = 0.f;
        #pragma unroll
        for (int d = 0; d < 32; d++) {
            int dp = (d + tid) & 31;
            s += Pact[base + dp] * Gact[base + dp];
        }
        size_t i = i0 + r;
        int m = (int)(i & 255), n = (int)((i >> 8) & 255), b = (int)(i >> 16);
        g_eattn[(((size_t)(b*NH + h)*NN + n)*NN) + m] = s;
    }
}

// ---------------- fused attention: scores + bias + mask + softmax + attn@V ----------------
// grid = BB*NH*8 (128 blocks), 256 threads, one block = (b, h, 32 query rows)
#define AKS 264     // Kt / Ps row stride (floats)
#define AVS 36      // V row stride
#define AQS 33      // Q row stride
#define ATT_SMEM ((32*AKS + 256*AVS + 32*AQS + 32*AKS) * 4)   // 108672 B

__global__ __launch_bounds__(256, 1)
void attention_kernel(const int* __restrict__ adj)
{
    extern __shared__ float smf[];
    float* Kt = smf;                 // [32 d][AKS]  (transposed K)
    float* Vs = Kt + 32*AKS;         // [256 m][AVS]
    float* Qs = Vs + 256*AVS;        // [32 r][AQS]
    float* Ps = Qs + 32*AQS;         // [32 r][AKS]  (attention probs)

    int bid = blockIdx.x;            // b*64 + h*8 + nb
    int nb = bid & 7, h = (bid >> 3) & 7, b = bid >> 6;
    int n0 = nb * 32;
    int tid = threadIdx.x;

    // load K (transposed) and V, coalesced reads
    const float* kbase = g_k + (size_t)(b*NN)*HIDD + h*DH;
    const float* vbase = g_v + (size_t)(b*NN)*HIDD + h*DH;
    #pragma unroll
    for (int it = 0; it < 32; it++) {
        int idx = tid + it*256;
        int m = idx >> 5, d = idx & 31;
        float kv = kbase[(size_t)m*HIDD + d];
        float vv = vbase[(size_t)m*HIDD + d];
        Kt[d*AKS + m] = kv;
        Vs[m*AVS + d] = vv;
    }
    // load Q rows n0..n0+31
    #pragma unroll
    for (int it = 0; it < 4; it++) {
        int idx = tid + it*256;
        int r = idx >> 5, d = idx & 31;
        Qs[r*AQS + d] = g_q[(size_t)(b*NN + n0 + r)*HIDD + h*DH + d];
    }
    __syncthreads();

    int r = tid >> 3, cg = tid & 7;   // row 0..31, col-group 0..7
    // thread owns m = cg*4 + c*32 + j  (c=0..7, j=0..3)

    // ---- scores = Q K^T ----
    float acc[8][4];
    #pragma unroll
    for (int c = 0; c < 8; c++)
        #pragma unroll
        for (int j = 0; j < 4; j++) acc[c][j] = 0.f;

    #pragma unroll
    for (int d = 0; d < 32; d++) {
        float qd = Qs[r*AQS + d];
        const float* krow = Kt + d*AKS + cg*4;
        #pragma unroll
        for (int c = 0; c < 8; c++) {
            float4 kv = *(const float4*)(krow + c*32);
            acc[c][0] = fmaf(qd, kv.x, acc[c][0]);
            acc[c][1] = fmaf(qd, kv.y, acc[c][1]);
            acc[c][2] = fmaf(qd, kv.z, acc[c][2]);
            acc[c][3] = fmaf(qd, kv.w, acc[c][3]);
        }
    }

    // ---- + eattn, mask, softmax (row split across 8 lanes) ----
    size_t rowbase = ((size_t)(b*NH + h)*NN + (n0 + r)) * NN;
    const float* erow = g_eattn + rowbase;
    const int*   arow = adj + (size_t)(b*NN + n0 + r)*NN;

    const float scale = 0.17677669529663687f;  // 1/sqrt(32)
    float mx = -1e30f;
    #pragma unroll
    for (int c = 0; c < 8; c++) {
        int m0 = cg*4 + c*32;
        float4 ev = *(const float4*)(erow + m0);
        int4   av = *(const int4*)(arow + m0);
        acc[c][0] = (av.x == 0) ? -1e9f : fmaf(acc[c][0], scale, ev.x);
        acc[c][1] = (av.y == 0) ? -1e9f : fmaf(acc[c][1], scale, ev.y);
        acc[c][2] = (av.z == 0) ? -1e9f : fmaf(acc[c][2], scale, ev.z);
        acc[c][3] = (av.w == 0) ? -1e9f : fmaf(acc[c][3], scale, ev.w);
        #pragma unroll
        for (int j = 0; j < 4; j++) mx = fmaxf(mx, acc[c][j]);
    }
    #pragma unroll
    for (int o = 1; o < 8; o <<= 1) mx = fmaxf(mx, __shfl_xor_sync(0xffffffffu, mx, o));

    float sum = 0.f;
    #pragma unroll
    for (int c = 0; c < 8; c++)
        #pragma unroll
        for (int j = 0; j < 4; j++) {
            acc[c][j] = __expf(acc[c][j] - mx);
            sum += acc[c][j];
        }
    #pragma unroll
    for (int o = 1; o < 8; o <<= 1) sum += __shfl_xor_sync(0xffffffffu, sum, o);
    float inv = 1.f / sum;

    // write probs to smem (for AV) and to gmem (for attn_mean)
    float* psrow = Ps + r*AKS;
    float* grow  = g_scores + rowbase;
    #pragma unroll
    for (int c = 0; c < 8; c++) {
        int m0 = cg*4 + c*32;
        float4 p;
        p.x = acc[c][0] * inv; p.y = acc[c][1] * inv;
        p.z = acc[c][2] * inv; p.w = acc[c][3] * inv;
        *(float4*)(psrow + m0) = p;
        *(float4*)(grow + m0)  = p;
    }
    __syncwarp();   // each row is produced entirely within one warp

    // ---- attn @ V : thread computes out[r][cg*4 .. cg*4+3] ----
    float o0 = 0.f, o1 = 0.f, o2 = 0.f, o3 = 0.f;
    #pragma unroll 8
    for (int m = 0; m < 256; m++) {
        float p = psrow[m];
        float4 vv = *(const float4*)(Vs + m*AVS + cg*4);
        o0 = fmaf(p, vv.x, o0);
        o1 = fmaf(p, vv.y, o1);
        o2 = fmaf(p, vv.z, o2);
        o3 = fmaf(p, vv.w, o3);
    }
    float4 ov = {o0, o1, o2, o3};
    *(float4*)(g_ao + (size_t)(b*NN + n0 + r)*HIDD + h*DH + cg*4) = ov;
}

// ---------------- generic fp32 GEMM body: 32x64 tile, BK=32 ----------------
__device__ __forceinline__ void gemm_body(const float* __restrict__ A, const float* __restrict__ W,
                                          const float* __restrict__ bias, float* __restrict__ C,
                                          int M, int Nc, int K, int bx, int by)
{
    __shared__ float As[32][33];
    __shared__ float Ws[32][64];
    int tid = threadIdx.x;
    int r0 = by * 32, c0 = bx * 64;
    int ty = tid >> 4, tx = tid & 15;
    float acc[2][4] = {};

    for (int kc = 0; kc < K; kc += 32) {
        {
            int r = tid >> 3, c4 = tid & 7;
            float4 v = *(const float4*)(A + (size_t)(r0 + r)*K + kc + c4*4);
            As[c4*4+0][r] = v.x; As[c4*4+1][r] = v.y;
            As[c4*4+2][r] = v.z; As[c4*4+3][r] = v.w;
        }
        #pragma unroll
        for (int it = 0; it < 2; it++) {
            int j = tid + it*256;
            int rr = j >> 4, c4 = j & 15;
            *(float4*)(&Ws[rr][c4*4]) = *(const float4*)(W + (size_t)(kc + rr)*Nc + c0 + c4*4);
        }
        __syncthreads();
        #pragma unroll
        for (int k = 0; k < 32; k++) {
            float a0 = As[k][ty*2], a1 = As[k][ty*2+1];
            float4 bv = *(float4*)(&Ws[k][tx*4]);
            acc[0][0] = fmaf(a0, bv.x, acc[0][0]);
            acc[0][1] = fmaf(a0, bv.y, acc[0][1]);
            acc[0][2] = fmaf(a0, bv.z, acc[0][2]);
            acc[0][3] = fmaf(a0, bv.w, acc[0][3]);
            acc[1][0] = fmaf(a1, bv.x, acc[1][0]);
            acc[1][1] = fmaf(a1, bv.y, acc[1][1]);
            acc[1][2] = fmaf(a1, bv.z, acc[1][2]);
            acc[1][3] = fmaf(a1, bv.w, acc[1][3]);
        }
        __syncthreads();
    }
    #pragma unroll
    for (int i = 0; i < 2; i++)
        #pragma unroll
        for (int j = 0; j < 4; j++) {
            int cc = c0 + tx*4 + j;
            float v = acc[i][j];
            if (bias) v += bias[cc];
            C[(size_t)(r0 + ty*2 + i)*Nc + cc] = v;
        }
}

__global__ __launch_bounds__(256)
void gemm_one_kernel(const float* __restrict__ A, const float* __restrict__ W,
                     const float* __restrict__ bias, float* __restrict__ C,
                     int M, int Nc, int K)
{
    gemm_body(A, W, bias, C, M, Nc, K, blockIdx.x, blockIdx.y);
}

__global__ __launch_bounds__(256)
void gemm_qkv_kernel(const float* __restrict__ A,
                     const float* __restrict__ Wq, const float* __restrict__ bq,
                     const float* __restrict__ Wk, const float* __restrict__ bk,
                     const float* __restrict__ Wv, const float* __restrict__ bv,
                     float* __restrict__ oq, float* __restrict__ ok, float* __restrict__ ov)
{
    int z = blockIdx.z;
    const float* W = (z == 0) ? Wq : (z == 1) ? Wk : Wv;
    const float* bb = (z == 0) ? bq : (z == 1) ? bk : bv;
    float* C = (z == 0) ? oq : (z == 1) ? ok : ov;
    gemm_body(A, W, bb, C, 512, 256, 256, blockIdx.x, blockIdx.y);
}

// ---------------- attn mean over heads ----------------
__global__ __launch_bounds__(256)
void attn_mean_kernel()
{
    int j = blockIdx.x * 256 + threadIdx.x;
    int b = j >> 16, nm = j & 65535;
    float s = 0.f;
    #pragma unroll
    for (int h = 0; h < NH; h++) s += g_scores[(((size_t)(b*NH + h)) << 16) + nm];
    g_amean[j] = s * 0.125f;
}

// ---------------- h_out = LN(residual + o)  (warp per row) ----------------
__global__ __launch_bounds__(256)
void ln_node_kernel(const float* __restrict__ g1, const float* __restrict__ b1,
                    float* __restrict__ out)
{
    int row = blockIdx.x * 8 + (threadIdx.x >> 5);
    int lane = threadIdx.x & 31;
    const float* ha = g_h + (size_t)row*256;
    const float* ta = g_tmp + (size_t)row*256;
    float4 a0 = *(const float4*)(ha + lane*4);
    float4 t0 = *(const float4*)(ta + lane*4);
    float4 a1 = *(const float4*)(ha + 128 + lane*4);
    float4 t1 = *(const float4*)(ta + 128 + lane*4);
    float x[8] = {a0.x+t0.x, a0.y+t0.y, a0.z+t0.z, a0.w+t0.w,
                  a1.x+t1.x, a1.y+t1.y, a1.z+t1.z, a1.w+t1.w};
    float s = 0.f;
    #pragma unroll
    for (int j = 0; j < 8; j++) s += x[j];
    float mean = warpSum(s) * (1.f/256.f);
    float vs = 0.f;
    #pragma unroll
    for (int j = 0; j < 8; j++) { float d = x[j] - mean; vs += d*d; }
    float inv = rsqrtf(warpSum(vs) * (1.f/256.f) + LN_EPS);
    float* o = out + (size_t)row*256;
    #pragma unroll
    for (int j = 0; j < 8; j++) {
        int c = (j < 4) ? (lane*4 + j) : (128 + lane*4 + j - 4);
        o[c] = (x[j] - mean) * inv * g1[c] + b1[c];
    }
}

// ---------------- edge_out = LN(E + amean*0.5*(P_n + P_m) + beo)  (warp per row) ----------------
__global__ __launch_bounds__(256)
void edge_out_kernel(const float* __restrict__ E, const float* __restrict__ beo,
                     const float* __restrict__ g2, const float* __restrict__ b2,
                     float* __restrict__ out)
{
    size_t i = (size_t)blockIdx.x * 8 + (threadIdx.x >> 5);
    int lane = threadIdx.x & 31;
    int m = (int)(i & 255), n = (int)((i >> 8) & 255), b = (int)(i >> 16);
    float am = g_amean[i] * 0.5f;
    const float* Er = E + i*256;
    const float* Pn = g_P + (size_t)(b*NN + n)*256;
    const float* Pm = g_P + (size_t)(b*NN + m)*256;

    float x[8];
    #pragma unroll
    for (int half = 0; half < 2; half++) {
        int c = half*128 + lane*4;
        float4 e  = *(const float4*)(Er + c);
        float4 pn = *(const float4*)(Pn + c);
        float4 pm = *(const float4*)(Pm + c);
        float4 bo = *(const float4*)(beo + c);
        x[half*4+0] = e.x + am*(pn.x + pm.x) + bo.x;
        x[half*4+1] = e.y + am*(pn.y + pm.y) + bo.y;
        x[half*4+2] = e.z + am*(pn.z + pm.z) + bo.z;
        x[half*4+3] = e.w + am*(pn.w + pm.w) + bo.w;
    }
    float s = 0.f;
    #pragma unroll
    for (int j = 0; j < 8; j++) s += x[j];
    float mean = warpSum(s) * (1.f/256.f);
    float vs = 0.f;
    #pragma unroll
    for (int j = 0; j < 8; j++) { float d = x[j] - mean; vs += d*d; }
    float inv = rsqrtf(warpSum(vs) * (1.f/256.f) + LN_EPS);
    float* o = out + i*256;
    #pragma unroll
    for (int half = 0; half < 2; half++) {
        int c = half*128 + lane*4;
        float4 gg = *(const float4*)(g2 + c);
        float4 bb = *(const float4*)(b2 + c);
        float4 r;
        r.x = (x[half*4+0] - mean) * inv * gg.x + bb.x;
        r.y = (x[half*4+1] - mean) * inv * gg.y + bb.y;
        r.z = (x[half*4+2] - mean) * inv * gg.z + bb.z;
        r.w = (x[half*4+3] - mean) * inv * gg.w + bb.w;
        *(float4*)(o + c) = r;
    }
}

// ---------------- launch ----------------
extern "C" void kernel_launch(void* const* d_in, const int* in_sizes, int n_in,
                              void* d_out, int out_size)
{
    const float* node = (const float*)d_in[0];
    const float* edge = (const float*)d_in[1];
    const int*   adj  = (const int*)  d_in[2];
    const float* Wn  = (const float*)d_in[3];  const float* bn  = (const float*)d_in[4];
    const float* Wq  = (const float*)d_in[5];  const float* bq  = (const float*)d_in[6];
    const float* Wk  = (const float*)d_in[7];  const float* bk  = (const float*)d_in[8];
    const float* Wv  = (const float*)d_in[9];  const float* bv  = (const float*)d_in[10];
    const float* Wep = (const float*)d_in[11]; const float* bep = (const float*)d_in[12];
    const float* Weg = (const float*)d_in[13]; const float* beg = (const float*)d_in[14];
    const float* Wo  = (const float*)d_in[15]; const float* bo  = (const float*)d_in[16];
    const float* Weo = (const float*)d_in[17]; const float* beo = (const float*)d_in[18];
    const float* g1  = (const float*)d_in[19]; const float* b1  = (const float*)d_in[20];
    const float* g2  = (const float*)d_in[21]; const float* b2  = (const float*)d_in[22];

    float* out   = (float*)d_out;
    float* h_out = out;
    float* e_out = out + (size_t)BB*NN*HIDD;

    float *ph, *pq, *pk, *pv, *pao, *ptmp, *pP;
    cudaGetSymbolAddress((void**)&ph,   g_h);
    cudaGetSymbolAddress((void**)&pq,   g_q);
    cudaGetSymbolAddress((void**)&pk,   g_k);
    cudaGetSymbolAddress((void**)&pv,   g_v);
    cudaGetSymbolAddress((void**)&pao,  g_ao);
    cudaGetSymbolAddress((void**)&ptmp, g_tmp);
    cudaGetSymbolAddress((void**)&pP,   g_P);

    cudaFuncSetAttribute(edge_attn_mma_kernel,
                         cudaFuncAttributeMaxDynamicSharedMemorySize, EDGE_SMEM);
    cudaFuncSetAttribute(attention_kernel,
                         cudaFuncAttributeMaxDynamicSharedMemorySize, ATT_SMEM);

    // weight convert (independent) + node projection
    cvt_w_kernel<<<512, 256>>>(Wep, Weg);
    gemm_one_kernel<<<dim3(4, 16), 256>>>(node, Wn, bn, ph, 512, 256, 128);

    // QKV in one launch
    gemm_qkv_kernel<<<dim3(4, 16, 3), 256>>>(ph, Wq, bq, Wk, bk, Wv, bv, pq, pk, pv);

    // edge bias (tensor cores), then fused attention
    edge_attn_mma_kernel<<<(BB*NN*NN)/64, 512, EDGE_SMEM>>>(edge, bep, beg);
    attention_kernel<<<BB*NH*8, 256, ATT_SMEM>>>(adj);

    // mean over heads (for edge update)
    attn_mean_kernel<<<(BB*NN*NN)/256, 256>>>();

    // out-proj + node LN
    gemm_one_kernel<<<dim3(4, 16), 256>>>(pao, Wo, bo, ptmp, 512, 256, 256);
    ln_node_kernel<<<(BB*NN)/8, 256>>>(g1, b1, h_out);

    // P = h_out @ Weo, then fused edge output LN
    gemm_one_kernel<<<dim3(4, 16), 256>>>(h_out, Weo, (const float*)nullptr, pP, 512, 256, 256);
    edge_out_kernel<<<(BB*NN*NN)/8, 256>>>(edge, beo, g2, b2, e_out);
}

// round 10
// speedup vs baseline: 4.1944x; 1.0983x over previous
#include <cuda_runtime.h>
#include <math.h>

// Problem dims
#define BB   2
#define NN   256
#define ND   128
#define ED   256
#define HIDD 256
#define NH   8
#define DH   32
#define LN_EPS 1e-5f

// ---------------- device scratch ----------------
__device__ float g_h   [BB*NN*HIDD];
__device__ float g_q   [BB*NN*HIDD];
__device__ float g_k   [BB*NN*HIDD];
__device__ float g_v   [BB*NN*HIDD];
__device__ float g_scores[BB*NH*NN*NN];   // attention probabilities
__device__ float g_eattn [BB*NH*NN*NN];
__device__ float g_amean [BB*NN*NN];
__device__ float g_ao  [BB*NN*HIDD];
__device__ float g_tmp [BB*NN*HIDD];
__device__ float g_P   [BB*NN*ED];
// tf32 bits of [Wep|Weg], pre-permuted into per-warp fragment order:
// index = ((((c*8 + cw)*4 + ks)*4 + q)*32 + lane)*4 + pos
// where v=q*4+pos, nt=v>>1, half=v&1, g=lane>>2, tig=lane&3,
//       k = c*32 + ks*8 + tig + half*4,  n = cw*64 + nt*8 + g
__device__ unsigned g_Wc[256*512];

// ---------------- helpers ----------------
__device__ __forceinline__ float warpSum(float v) {
    #pragma unroll
    for (int o = 16; o; o >>= 1) v += __shfl_xor_sync(0xffffffffu, v, o);
    return v;
}
__device__ __forceinline__ unsigned f2tf32(float x) {
    unsigned r;
    asm("cvt.rna.tf32.f32 %0, %1;" : "=r"(r) : "f"(x));
    return r;
}
__device__ __forceinline__ void mma_tf32(float* d, const unsigned* a, unsigned b0, unsigned b1) {
    asm volatile("mma.sync.aligned.m16n8k8.row.col.f32.tf32.tf32.f32 "
        "{%0,%1,%2,%3}, {%4,%5,%6,%7}, {%8,%9}, {%0,%1,%2,%3};"
        : "+f"(d[0]), "+f"(d[1]), "+f"(d[2]), "+f"(d[3])
        : "r"(a[0]), "r"(a[1]), "r"(a[2]), "r"(a[3]), "r"(b0), "r"(b1));
}
__device__ __forceinline__ void cp_async16(void* smem, const void* gmem) {
    unsigned saddr = (unsigned)__cvta_generic_to_shared(smem);
    asm volatile("cp.async.cg.shared.global [%0], [%1], 16;" :: "r"(saddr), "l"(gmem));
}
#define CP_COMMIT() asm volatile("cp.async.commit_group;")
#define CP_WAIT0()  asm volatile("cp.async.wait_group 0;")

// ---------------- weight pre-convert into fragment-ordered tf32 ----------------
__global__ __launch_bounds__(256)
void cvt_w_kernel(const float* __restrict__ Wep, const float* __restrict__ Weg)
{
    int o = blockIdx.x * 256 + threadIdx.x;   // 0..131071
    int pos  = o & 3;
    int lane = (o >> 2) & 31;
    int q    = (o >> 7) & 3;
    int ks   = (o >> 9) & 3;
    int cw   = (o >> 11) & 7;
    int c    = o >> 14;
    int v = q*4 + pos, nt = v >> 1, half = v & 1;
    int g = lane >> 2, tig = lane & 3;
    int k = c*32 + ks*8 + tig + half*4;
    int n = cw*64 + nt*8 + g;
    float val = (n < 256) ? Wep[k*256 + n] : Weg[k*256 + (n - 256)];
    g_Wc[o] = f2tf32(val);
}

// ---------------- edge projection + gate + head reduction (tf32 MMA) ----------------
// CTA: 64 E-rows x 512 cols, 512 threads, 8 chunks of k32, double buffered.
#define SAE 36
#define EA0 0
#define EA1 9216
#define EB0 18432
#define EB1 83968
#define EDGE_SMEM 149504

__global__ __launch_bounds__(512, 1)
void edge_attn_mma_kernel(const float* __restrict__ E,
                          const float* __restrict__ bep, const float* __restrict__ beg)
{
    extern __shared__ float sm[];
    char* smc = (char*)sm;
    int tid  = threadIdx.x;
    int lane = tid & 31, w = tid >> 5;
    int g    = lane >> 2, tig = lane & 3;
    int rh   = w >> 3;                   // row half (0/1)
    int cw   = w & 7;                    // col warp
    int col0 = cw * 64;
    size_t i0 = (size_t)blockIdx.x * 64;

    float acc[2][8][4];
    #pragma unroll
    for (int mi = 0; mi < 2; mi++)
        #pragma unroll
        for (int nt = 0; nt < 8; nt++)
            #pragma unroll
            for (int q = 0; q < 4; q++) acc[mi][nt][q] = 0.f;

    // each thread owns one float4 of the A tile per chunk
    const float* asrc = E + (i0 + (tid >> 3))*256 + (tid & 7)*4;
    unsigned aoff = (unsigned)((tid >> 3)*SAE + (tid & 7)*4);

    // prologue: chunk 0
    {
        float4 av = *(const float4*)(asrc);
        unsigned* Ad = (unsigned*)(smc + EA0) + aoff;
        Ad[0] = f2tf32(av.x); Ad[1] = f2tf32(av.y);
        Ad[2] = f2tf32(av.z); Ad[3] = f2tf32(av.w);
        #pragma unroll
        for (int t = 0; t < 8; t++) {
            int idx = tid + t*512;
            cp_async16(smc + EB0 + idx*16, g_Wc + (size_t)idx*4);
        }
        CP_COMMIT();
    }

    #pragma unroll 1
    for (int c = 0; c < 8; c++) {
        CP_WAIT0();
        __syncthreads();                      // chunk c resident in buf[c&1]

        float4 a_pre;
        if (c < 7) {
            a_pre = *(const float4*)(asrc + (c + 1)*32);       // LDG early (hidden by MMAs)
            char* Bb = smc + (((c + 1) & 1) ? EB1 : EB0);
            const unsigned* bsrc = g_Wc + (size_t)(c + 1)*16384;
            #pragma unroll
            for (int t = 0; t < 8; t++) {
                int idx = tid + t*512;
                cp_async16(Bb + idx*16, bsrc + idx*4);
            }
            CP_COMMIT();
        }

        const unsigned* Au = (const unsigned*)(smc + ((c & 1) ? EA1 : EA0));
        const unsigned* Bu = (const unsigned*)(smc + ((c & 1) ? EB1 : EB0));
        #pragma unroll
        for (int ks = 0; ks < 4; ks++) {
            int k0 = ks * 8;
            unsigned a[2][4];
            #pragma unroll
            for (int mi = 0; mi < 2; mi++) {
                int r = rh*32 + mi*16 + g;
                a[mi][0] = Au[r*SAE + k0 + tig];
                a[mi][1] = Au[(r+8)*SAE + k0 + tig];
                a[mi][2] = Au[r*SAE + k0 + tig + 4];
                a[mi][3] = Au[(r+8)*SAE + k0 + tig + 4];
            }
            unsigned br[16];
            const uint4* bs = (const uint4*)(Bu + ((cw*4 + ks) << 9));
            *(uint4*)(br + 0)  = bs[lane];
            *(uint4*)(br + 4)  = bs[32 + lane];
            *(uint4*)(br + 8)  = bs[64 + lane];
            *(uint4*)(br + 12) = bs[96 + lane];
            #pragma unroll
            for (int nt = 0; nt < 8; nt++) {
                mma_tf32(acc[0][nt], a[0], br[2*nt], br[2*nt + 1]);
                mma_tf32(acc[1][nt], a[1], br[2*nt], br[2*nt + 1]);
            }
        }

        if (c < 7) {                          // STS of prefetched A after MMAs
            unsigned* Ad = (unsigned*)(smc + (((c + 1) & 1) ? EA1 : EA0)) + aoff;
            Ad[0] = f2tf32(a_pre.x); Ad[1] = f2tf32(a_pre.y);
            Ad[2] = f2tf32(a_pre.z); Ad[3] = f2tf32(a_pre.w);
        }
        __syncthreads();
    }

    // epilogue: bias (+sigmoid for gate), stage to smem [64][264]
    float* Pact = sm;
    float* Gact = sm + 64*264;
    #pragma unroll
    for (int mi = 0; mi < 2; mi++)
        #pragma unroll
        for (int nt = 0; nt < 8; nt++) {
            int colg = col0 + nt*8 + tig*2;
            int r0 = rh*32 + mi*16 + g;
            if (cw < 4) {
                float b0v = bep[colg], b1v = bep[colg+1];
                Pact[r0*264 + colg]       = acc[mi][nt][0] + b0v;
                Pact[r0*264 + colg + 1]   = acc[mi][nt][1] + b1v;
                Pact[(r0+8)*264 + colg]   = acc[mi][nt][2] + b0v;
                Pact[(r0+8)*264 + colg+1] = acc[mi][nt][3] + b1v;
            } else {
                int cc = colg - 256;
                float b0v = beg[cc], b1v = beg[cc+1];
                float s0 = acc[mi][nt][0] + b0v, s1 = acc[mi][nt][1] + b1v;
                float s2 = acc[mi][nt][2] + b0v, s3 = acc[mi][nt][3] + b1v;
                Gact[r0*264 + cc]       = 1.f / (1.f + __expf(-s0));
                Gact[r0*264 + cc + 1]   = 1.f / (1.f + __expf(-s1));
                Gact[(r0+8)*264 + cc]   = 1.f / (1.f + __expf(-s2));
                Gact[(r0+8)*264 + cc+1] = 1.f / (1.f + __expf(-s3));
            }
        }
    __syncthreads();

    // per-head gated reduction: 64 rows x 8 heads = 512 outputs
    {
        int r = tid >> 3, h = tid & 7;
        int base = r*264 + h*32;
        float s = 0.f;
        #pragma unroll
        for (int d = 0; d < 32; d++) {
            int dp = (d + tid) & 31;
            s += Pact[base + dp] * Gact[base + dp];
        }
        size_t i = i0 + r;
        int m = (int)(i & 255), n = (int)((i >> 8) & 255), b = (int)(i >> 16);
        g_eattn[(((size_t)(b*NH + h)*NN + n)*NN) + m] = s;
    }
}

// ---------------- fused attention: scores + bias + mask + softmax + attn@V ----------------
#define AKS 264
#define AVS 36
#define AQS 33
#define ATT_SMEM ((32*AKS + 256*AVS + 32*AQS + 32*AKS) * 4)

__global__ __launch_bounds__(256, 1)
void attention_kernel(const int* __restrict__ adj)
{
    extern __shared__ float smf[];
    float* Kt = smf;
    float* Vs = Kt + 32*AKS;
    float* Qs = Vs + 256*AVS;
    float* Ps = Qs + 32*AQS;

    int bid = blockIdx.x;
    int nb = bid & 7, h = (bid >> 3) & 7, b = bid >> 6;
    int n0 = nb * 32;
    int tid = threadIdx.x;

    const float* kbase = g_k + (size_t)(b*NN)*HIDD + h*DH;
    const float* vbase = g_v + (size_t)(b*NN)*HIDD + h*DH;
    #pragma unroll
    for (int it = 0; it < 32; it++) {
        int idx = tid + it*256;
        int m = idx >> 5, d = idx & 31;
        float kv = kbase[(size_t)m*HIDD + d];
        float vv = vbase[(size_t)m*HIDD + d];
        Kt[d*AKS + m] = kv;
        Vs[m*AVS + d] = vv;
    }
    #pragma unroll
    for (int it = 0; it < 4; it++) {
        int idx = tid + it*256;
        int r = idx >> 5, d = idx & 31;
        Qs[r*AQS + d] = g_q[(size_t)(b*NN + n0 + r)*HIDD + h*DH + d];
    }
    __syncthreads();

    int r = tid >> 3, cg = tid & 7;

    float acc[8][4];
    #pragma unroll
    for (int c = 0; c < 8; c++)
        #pragma unroll
        for (int j = 0; j < 4; j++) acc[c][j] = 0.f;

    #pragma unroll
    for (int d = 0; d < 32; d++) {
        float qd = Qs[r*AQS + d];
        const float* krow = Kt + d*AKS + cg*4;
        #pragma unroll
        for (int c = 0; c < 8; c++) {
            float4 kv = *(const float4*)(krow + c*32);
            acc[c][0] = fmaf(qd, kv.x, acc[c][0]);
            acc[c][1] = fmaf(qd, kv.y, acc[c][1]);
            acc[c][2] = fmaf(qd, kv.z, acc[c][2]);
            acc[c][3] = fmaf(qd, kv.w, acc[c][3]);
        }
    }

    size_t rowbase = ((size_t)(b*NH + h)*NN + (n0 + r)) * NN;
    const float* erow = g_eattn + rowbase;
    const int*   arow = adj + (size_t)(b*NN + n0 + r)*NN;

    const float scale = 0.17677669529663687f;
    float mx = -1e30f;
    #pragma unroll
    for (int c = 0; c < 8; c++) {
        int m0 = cg*4 + c*32;
        float4 ev = *(const float4*)(erow + m0);
        int4   av = *(const int4*)(arow + m0);
        acc[c][0] = (av.x == 0) ? -1e9f : fmaf(acc[c][0], scale, ev.x);
        acc[c][1] = (av.y == 0) ? -1e9f : fmaf(acc[c][1], scale, ev.y);
        acc[c][2] = (av.z == 0) ? -1e9f : fmaf(acc[c][2], scale, ev.z);
        acc[c][3] = (av.w == 0) ? -1e9f : fmaf(acc[c][3], scale, ev.w);
        #pragma unroll
        for (int j = 0; j < 4; j++) mx = fmaxf(mx, acc[c][j]);
    }
    #pragma unroll
    for (int o = 1; o < 8; o <<= 1) mx = fmaxf(mx, __shfl_xor_sync(0xffffffffu, mx, o));

    float sum = 0.f;
    #pragma unroll
    for (int c = 0; c < 8; c++)
        #pragma unroll
        for (int j = 0; j < 4; j++) {
            acc[c][j] = __expf(acc[c][j] - mx);
            sum += acc[c][j];
        }
    #pragma unroll
    for (int o = 1; o < 8; o <<= 1) sum += __shfl_xor_sync(0xffffffffu, sum, o);
    float inv = 1.f / sum;

    float* psrow = Ps + r*AKS;
    float* grow  = g_scores + rowbase;
    #pragma unroll
    for (int c = 0; c < 8; c++) {
        int m0 = cg*4 + c*32;
        float4 p;
        p.x = acc[c][0] * inv; p.y = acc[c][1] * inv;
        p.z = acc[c][2] * inv; p.w = acc[c][3] * inv;
        *(float4*)(psrow + m0) = p;
        *(float4*)(grow + m0)  = p;
    }
    __syncwarp();

    float o0 = 0.f, o1 = 0.f, o2 = 0.f, o3 = 0.f;
    #pragma unroll 8
    for (int m = 0; m < 256; m++) {
        float p = psrow[m];
        float4 vv = *(const float4*)(Vs + m*AVS + cg*4);
        o0 = fmaf(p, vv.x, o0);
        o1 = fmaf(p, vv.y, o1);
        o2 = fmaf(p, vv.z, o2);
        o3 = fmaf(p, vv.w, o3);
    }
    float4 ov = {o0, o1, o2, o3};
    *(float4*)(g_ao + (size_t)(b*NN + n0 + r)*HIDD + h*DH + cg*4) = ov;
}

// ---------------- generic fp32 GEMM body: 32x64 tile, BK=32 ----------------
__device__ __forceinline__ void gemm_body(const float* __restrict__ A, const float* __restrict__ W,
                                          const float* __restrict__ bias, float* __restrict__ C,
                                          int M, int Nc, int K, int bx, int by)
{
    __shared__ float As[32][33];
    __shared__ float Ws[32][64];
    int tid = threadIdx.x;
    int r0 = by * 32, c0 = bx * 64;
    int ty = tid >> 4, tx = tid & 15;
    float acc[2][4] = {};

    for (int kc = 0; kc < K; kc += 32) {
        {
            int r = tid >> 3, c4 = tid & 7;
            float4 v = *(const float4*)(A + (size_t)(r0 + r)*K + kc + c4*4);
            As[c4*4+0][r] = v.x; As[c4*4+1][r] = v.y;
            As[c4*4+2][r] = v.z; As[c4*4+3][r] = v.w;
        }
        #pragma unroll
        for (int it = 0; it < 2; it++) {
            int j = tid + it*256;
            int rr = j >> 4, c4 = j & 15;
            *(float4*)(&Ws[rr][c4*4]) = *(const float4*)(W + (size_t)(kc + rr)*Nc + c0 + c4*4);
        }
        __syncthreads();
        #pragma unroll
        for (int k = 0; k < 32; k++) {
            float a0 = As[k][ty*2], a1 = As[k][ty*2+1];
            float4 bv = *(float4*)(&Ws[k][tx*4]);
            acc[0][0] = fmaf(a0, bv.x, acc[0][0]);
            acc[0][1] = fmaf(a0, bv.y, acc[0][1]);
            acc[0][2] = fmaf(a0, bv.z, acc[0][2]);
            acc[0][3] = fmaf(a0, bv.w, acc[0][3]);
            acc[1][0] = fmaf(a1, bv.x, acc[1][0]);
            acc[1][1] = fmaf(a1, bv.y, acc[1][1]);
            acc[1][2] = fmaf(a1, bv.z, acc[1][2]);
            acc[1][3] = fmaf(a1, bv.w, acc[1][3]);
        }
        __syncthreads();
    }
    #pragma unroll
    for (int i = 0; i < 2; i++)
        #pragma unroll
        for (int j = 0; j < 4; j++) {
            int cc = c0 + tx*4 + j;
            float v = acc[i][j];
            if (bias) v += bias[cc];
            C[(size_t)(r0 + ty*2 + i)*Nc + cc] = v;
        }
}

__global__ __launch_bounds__(256)
void gemm_one_kernel(const float* __restrict__ A, const float* __restrict__ W,
                     const float* __restrict__ bias, float* __restrict__ C,
                     int M, int Nc, int K)
{
    gemm_body(A, W, bias, C, M, Nc, K, blockIdx.x, blockIdx.y);
}

__global__ __launch_bounds__(256)
void gemm_qkv_kernel(const float* __restrict__ A,
                     const float* __restrict__ Wq, const float* __restrict__ bq,
                     const float* __restrict__ Wk, const float* __restrict__ bk,
                     const float* __restrict__ Wv, const float* __restrict__ bv,
                     float* __restrict__ oq, float* __restrict__ ok, float* __restrict__ ov)
{
    int z = blockIdx.z;
    const float* W = (z == 0) ? Wq : (z == 1) ? Wk : Wv;
    const float* bb = (z == 0) ? bq : (z == 1) ? bk : bv;
    float* C = (z == 0) ? oq : (z == 1) ? ok : ov;
    gemm_body(A, W, bb, C, 512, 256, 256, blockIdx.x, blockIdx.y);
}

// ---------------- attn mean over heads ----------------
__global__ __launch_bounds__(256)
void attn_mean_kernel()
{
    int j = blockIdx.x * 256 + threadIdx.x;
    int b = j >> 16, nm = j & 65535;
    float s = 0.f;
    #pragma unroll
    for (int h = 0; h < NH; h++) s += g_scores[(((size_t)(b*NH + h)) << 16) + nm];
    g_amean[j] = s * 0.125f;
}

// ---------------- h_out = LN(residual + o)  (warp per row) ----------------
__global__ __launch_bounds__(256)
void ln_node_kernel(const float* __restrict__ g1, const float* __restrict__ b1,
                    float* __restrict__ out)
{
    int row = blockIdx.x * 8 + (threadIdx.x >> 5);
    int lane = threadIdx.x & 31;
    const float* ha = g_h + (size_t)row*256;
    const float* ta = g_tmp + (size_t)row*256;
    float4 a0 = *(const float4*)(ha + lane*4);
    float4 t0 = *(const float4*)(ta + lane*4);
    float4 a1 = *(const float4*)(ha + 128 + lane*4);
    float4 t1 = *(const float4*)(ta + 128 + lane*4);
    float x[8] = {a0.x+t0.x, a0.y+t0.y, a0.z+t0.z, a0.w+t0.w,
                  a1.x+t1.x, a1.y+t1.y, a1.z+t1.z, a1.w+t1.w};
    float s = 0.f;
    #pragma unroll
    for (int j = 0; j < 8; j++) s += x[j];
    float mean = warpSum(s) * (1.f/256.f);
    float vs = 0.f;
    #pragma unroll
    for (int j = 0; j < 8; j++) { float d = x[j] - mean; vs += d*d; }
    float inv = rsqrtf(warpSum(vs) * (1.f/256.f) + LN_EPS);
    float* o = out + (size_t)row*256;
    #pragma unroll
    for (int j = 0; j < 8; j++) {
        int c = (j < 4) ? (lane*4 + j) : (128 + lane*4 + j - 4);
        o[c] = (x[j] - mean) * inv * g1[c] + b1[c];
    }
}

// ---------------- edge_out = LN(E + amean*0.5*(P_n + P_m) + beo)  (warp per row) ----------------
__global__ __launch_bounds__(256)
void edge_out_kernel(const float* __restrict__ E, const float* __restrict__ beo,
                     const float* __restrict__ g2, const float* __restrict__ b2,
                     float* __restrict__ out)
{
    size_t i = (size_t)blockIdx.x * 8 + (threadIdx.x >> 5);
    int lane = threadIdx.x & 31;
    int m = (int)(i & 255), n = (int)((i >> 8) & 255), b = (int)(i >> 16);
    float am = g_amean[i] * 0.5f;
    const float* Er = E + i*256;
    const float* Pn = g_P + (size_t)(b*NN + n)*256;
    const float* Pm = g_P + (size_t)(b*NN + m)*256;

    float x[8];
    #pragma unroll
    for (int half = 0; half < 2; half++) {
        int c = half*128 + lane*4;
        float4 e  = *(const float4*)(Er + c);
        float4 pn = *(const float4*)(Pn + c);
        float4 pm = *(const float4*)(Pm + c);
        float4 bo = *(const float4*)(beo + c);
        x[half*4+0] = e.x + am*(pn.x + pm.x) + bo.x;
        x[half*4+1] = e.y + am*(pn.y + pm.y) + bo.y;
        x[half*4+2] = e.z + am*(pn.z + pm.z) + bo.z;
        x[half*4+3] = e.w + am*(pn.w + pm.w) + bo.w;
    }
    float s = 0.f;
    #pragma unroll
    for (int j = 0; j < 8; j++) s += x[j];
    float mean = warpSum(s) * (1.f/256.f);
    float vs = 0.f;
    #pragma unroll
    for (int j = 0; j < 8; j++) { float d = x[j] - mean; vs += d*d; }
    float inv = rsqrtf(warpSum(vs) * (1.f/256.f) + LN_EPS);
    float* o = out + i*256;
    #pragma unroll
    for (int half = 0; half < 2; half++) {
        int c = half*128 + lane*4;
        float4 gg = *(const float4*)(g2 + c);
        float4 bb = *(const float4*)(b2 + c);
        float4 r;
        r.x = (x[half*4+0] - mean) * inv * gg.x + bb.x;
        r.y = (x[half*4+1] - mean) * inv * gg.y + bb.y;
        r.z = (x[half*4+2] - mean) * inv * gg.z + bb.z;
        r.w = (x[half*4+3] - mean) * inv * gg.w + bb.w;
        *(float4*)(o + c) = r;
    }
}

// ---------------- launch ----------------
extern "C" void kernel_launch(void* const* d_in, const int* in_sizes, int n_in,
                              void* d_out, int out_size)
{
    const float* node = (const float*)d_in[0];
    const float* edge = (const float*)d_in[1];
    const int*   adj  = (const int*)  d_in[2];
    const float* Wn  = (const float*)d_in[3];  const float* bn  = (const float*)d_in[4];
    const float* Wq  = (const float*)d_in[5];  const float* bq  = (const float*)d_in[6];
    const float* Wk  = (const float*)d_in[7];  const float* bk  = (const float*)d_in[8];
    const float* Wv  = (const float*)d_in[9];  const float* bv  = (const float*)d_in[10];
    const float* Wep = (const float*)d_in[11]; const float* bep = (const float*)d_in[12];
    const float* Weg = (const float*)d_in[13]; const float* beg = (const float*)d_in[14];
    const float* Wo  = (const float*)d_in[15]; const float* bo  = (const float*)d_in[16];
    const float* Weo = (const float*)d_in[17]; const float* beo = (const float*)d_in[18];
    const float* g1  = (const float*)d_in[19]; const float* b1  = (const float*)d_in[20];
    const float* g2  = (const float*)d_in[21]; const float* b2  = (const float*)d_in[22];

    float* out   = (float*)d_out;
    float* h_out = out;
    float* e_out = out + (size_t)BB*NN*HIDD;

    float *ph, *pq, *pk, *pv, *pao, *ptmp, *pP;
    cudaGetSymbolAddress((void**)&ph,   g_h);
    cudaGetSymbolAddress((void**)&pq,   g_q);
    cudaGetSymbolAddress((void**)&pk,   g_k);
    cudaGetSymbolAddress((void**)&pv,   g_v);
    cudaGetSymbolAddress((void**)&pao,  g_ao);
    cudaGetSymbolAddress((void**)&ptmp, g_tmp);
    cudaGetSymbolAddress((void**)&pP,   g_P);

    cudaFuncSetAttribute(edge_attn_mma_kernel,
                         cudaFuncAttributeMaxDynamicSharedMemorySize, EDGE_SMEM);
    cudaFuncSetAttribute(attention_kernel,
                         cudaFuncAttributeMaxDynamicSharedMemorySize, ATT_SMEM);

    // weight convert/permute (independent) + node projection
    cvt_w_kernel<<<512, 256>>>(Wep, Weg);
    gemm_one_kernel<<<dim3(4, 16), 256>>>(node, Wn, bn, ph, 512, 256, 128);

    // QKV in one launch
    gemm_qkv_kernel<<<dim3(4, 16, 3), 256>>>(ph, Wq, bq, Wk, bk, Wv, bv, pq, pk, pv);

    // edge bias (tensor cores), then fused attention
    edge_attn_mma_kernel<<<(BB*NN*NN)/64, 512, EDGE_SMEM>>>(edge, bep, beg);
    attention_kernel<<<BB*NH*8, 256, ATT_SMEM>>>(adj);

    // mean over heads (for edge update)
    attn_mean_kernel<<<(BB*NN*NN)/256, 256>>>();

    // out-proj + node LN
    gemm_one_kernel<<<dim3(4, 16), 256>>>(pao, Wo, bo, ptmp, 512, 256, 256);
    ln_node_kernel<<<(BB*NN)/8, 256>>>(g1, b1, h_out);

    // P = h_out @ Weo, then fused edge output LN
    gemm_one_kernel<<<dim3(4, 16), 256>>>(h_out, Weo, (const float*)nullptr, pP, 512, 256, 256);
    edge_out_kernel<<<(BB*NN*NN)/8, 256>>>(edge, beo, g2, b2, e_out);
}

// round 14
// speedup vs baseline: 5.1424x; 1.2260x over previous
#include <cuda_runtime.h>
#include <cuda_bf16.h>
#include <math.h>

// Problem dims
#define BB   2
#define NN   256
#define ND   128
#define ED   256
#define HIDD 256
#define NH   8
#define DH   32
#define LN_EPS 1e-5f

// ---------------- device scratch ----------------
__device__ float g_h   [BB*NN*HIDD];
__device__ float g_q   [BB*NN*HIDD];
__device__ float g_k   [BB*NN*HIDD];
__device__ float g_v   [BB*NN*HIDD];
__device__ float g_scores[BB*NH*NN*NN];   // attention probabilities
__device__ float g_eattn [BB*NH*NN*NN];
__device__ float g_amean [BB*NN*NN];
__device__ float g_ao  [BB*NN*HIDD];
__device__ float g_tmp [BB*NN*HIDD];
__device__ float g_P   [BB*NN*ED];
// bf16x2 of [Wep|Weg], pre-permuted into per-warp m16n8k16 fragment order:
// word index o = ((((c*8 + cw)*2 + step)*4 + q)*32 + lane)*4 + pos
// reg = q*4+pos, nt = reg>>1, half = reg&1, g = lane>>2, tig = lane&3
// k pair = c*32 + step*16 + tig*2 + half*8 (+1),  n = cw*64 + nt*8 + g
__device__ unsigned g_Wc[65536];

// ---------------- helpers ----------------
__device__ __forceinline__ float warpSum(float v) {
    #pragma unroll
    for (int o = 16; o; o >>= 1) v += __shfl_xor_sync(0xffffffffu, v, o);
    return v;
}
__device__ __forceinline__ unsigned pack_bf16(float lo, float hi) {
    __nv_bfloat162 p = __floats2bfloat162_rn(lo, hi);
    return *(unsigned*)&p;
}
__device__ __forceinline__ void mma_bf16(float* d, const unsigned* a, unsigned b0, unsigned b1) {
    asm volatile("mma.sync.aligned.m16n8k16.row.col.f32.bf16.bf16.f32 "
        "{%0,%1,%2,%3}, {%4,%5,%6,%7}, {%8,%9}, {%0,%1,%2,%3};"
        : "+f"(d[0]), "+f"(d[1]), "+f"(d[2]), "+f"(d[3])
        : "r"(a[0]), "r"(a[1]), "r"(a[2]), "r"(a[3]), "r"(b0), "r"(b1));
}
__device__ __forceinline__ void cp_async16(void* smem, const void* gmem) {
    unsigned saddr = (unsigned)__cvta_generic_to_shared(smem);
    asm volatile("cp.async.cg.shared.global [%0], [%1], 16;" :: "r"(saddr), "l"(gmem));
}
#define CP_COMMIT() asm volatile("cp.async.commit_group;")
#define CP_WAIT0()  asm volatile("cp.async.wait_group 0;")

// ---------------- weight pre-convert into fragment-ordered bf16 ----------------
__global__ __launch_bounds__(256)
void cvt_w_kernel(const float* __restrict__ Wep, const float* __restrict__ Weg)
{
    int o = blockIdx.x * 256 + threadIdx.x;   // 0..65535
    int pos  = o & 3;
    int lane = (o >> 2) & 31;
    int q    = (o >> 7) & 3;
    int step = (o >> 9) & 1;
    int cw   = (o >> 10) & 7;
    int c    = o >> 13;
    int reg = q*4 + pos, nt = reg >> 1, half = reg & 1;
    int g = lane >> 2, tig = lane & 3;
    int k = c*32 + step*16 + tig*2 + half*8;
    int n = cw*64 + nt*8 + g;
    float lo, hi;
    if (n < 256) { lo = Wep[k*256 + n];       hi = Wep[(k+1)*256 + n]; }
    else         { lo = Weg[k*256 + n - 256]; hi = Weg[(k+1)*256 + n - 256]; }
    g_Wc[o] = pack_bf16(lo, hi);
}

// ---------------- edge projection + gate + head reduction (bf16 MMA) ----------------
// CTA: 64 E-rows x 512 cols, 512 threads, 8 chunks of k32, double buffered.
// A tile: bf16, 64 rows x 32 k, row stride 20 b32 words (conflict-free)
#define EAW 20
#define EA0 0
#define EA1 5120
#define EB0 10240
#define EB1 43008
#define EDGE_SMEM 135168     // epilogue: 2 * 64 * 264 floats

__global__ __launch_bounds__(512, 1)
void edge_attn_mma_kernel(const float* __restrict__ E,
                          const float* __restrict__ bep, const float* __restrict__ beg)
{
    extern __shared__ float sm[];
    char* smc = (char*)sm;
    int tid  = threadIdx.x;
    int lane = tid & 31, w = tid >> 5;
    int g    = lane >> 2, tig = lane & 3;
    int rh   = w >> 3;                   // row half (0/1)
    int cw   = w & 7;                    // col warp
    int col0 = cw * 64;
    size_t i0 = (size_t)blockIdx.x * 64;

    float acc[2][8][4];
    #pragma unroll
    for (int mi = 0; mi < 2; mi++)
        #pragma unroll
        for (int nt = 0; nt < 8; nt++)
            #pragma unroll
            for (int q = 0; q < 4; q++) acc[mi][nt][q] = 0.f;

    // each thread owns one float4 (4 consecutive k) of the A tile per chunk
    int tr = tid >> 3, kq = tid & 7;
    const float* asrc = E + (i0 + tr)*256 + kq*4;
    unsigned aoff = (unsigned)(tr*EAW + kq*2);     // b32 word offset

    // prologue: chunk 0
    {
        float4 av = *(const float4*)(asrc);
        unsigned* Ad = (unsigned*)(smc + EA0);
        uint2 wv = { pack_bf16(av.x, av.y), pack_bf16(av.z, av.w) };
        *(uint2*)(Ad + aoff) = wv;
        #pragma unroll
        for (int t = 0; t < 4; t++) {
            int idx = tid + t*512;
            cp_async16(smc + EB0 + idx*16, g_Wc + (size_t)idx*4);
        }
        CP_COMMIT();
    }

    #pragma unroll 1
    for (int c = 0; c < 8; c++) {
        CP_WAIT0();
        __syncthreads();                      // chunk c resident in buf[c&1]

        float4 a_pre;
        if (c < 7) {
            a_pre = *(const float4*)(asrc + (c + 1)*32);       // LDG early, hidden by MMAs
            char* Bb = smc + (((c + 1) & 1) ? EB1 : EB0);
            const unsigned* bsrc = g_Wc + (size_t)(c + 1)*8192;
            #pragma unroll
            for (int t = 0; t < 4; t++) {
                int idx = tid + t*512;
                cp_async16(Bb + idx*16, bsrc + idx*4);
            }
            CP_COMMIT();
        }

        const unsigned* Au = (const unsigned*)(smc + ((c & 1) ? EA1 : EA0));
        const unsigned* Bu = (const unsigned*)(smc + ((c & 1) ? EB1 : EB0));
        #pragma unroll
        for (int step = 0; step < 2; step++) {
            unsigned a[2][4];
            #pragma unroll
            for (int mi = 0; mi < 2; mi++) {
                int r = rh*32 + mi*16 + g;
                a[mi][0] = Au[r*EAW + step*8 + tig];
                a[mi][1] = Au[(r+8)*EAW + step*8 + tig];
                a[mi][2] = Au[r*EAW + step*8 + tig + 4];
                a[mi][3] = Au[(r+8)*EAW + step*8 + tig + 4];
            }
            unsigned br[16];
            const uint4* bs = (const uint4*)Bu + ((cw*2 + step) << 7);
            *(uint4*)(br + 0)  = bs[lane];
            *(uint4*)(br + 4)  = bs[32 + lane];
            *(uint4*)(br + 8)  = bs[64 + lane];
            *(uint4*)(br + 12) = bs[96 + lane];
            #pragma unroll
            for (int nt = 0; nt < 8; nt++) {
                mma_bf16(acc[0][nt], a[0], br[2*nt], br[2*nt + 1]);
                mma_bf16(acc[1][nt], a[1], br[2*nt], br[2*nt + 1]);
            }
        }

        if (c < 7) {                          // STS of prefetched A after MMAs
            unsigned* Ad = (unsigned*)(smc + (((c + 1) & 1) ? EA1 : EA0));
            uint2 wv = { pack_bf16(a_pre.x, a_pre.y), pack_bf16(a_pre.z, a_pre.w) };
            *(uint2*)(Ad + aoff) = wv;
        }
        __syncthreads();
    }

    // epilogue: bias (+sigmoid for gate), stage to smem [64][264]
    float* Pact = sm;
    float* Gact = sm + 64*264;
    #pragma unroll
    for (int mi = 0; mi < 2; mi++)
        #pragma unroll
        for (int nt = 0; nt < 8; nt++) {
            int colg = col0 + nt*8 + tig*2;
            int r0 = rh*32 + mi*16 + g;
            if (cw < 4) {
                float b0v = bep[colg], b1v = bep[colg+1];
                Pact[r0*264 + colg]       = acc[mi][nt][0] + b0v;
                Pact[r0*264 + colg + 1]   = acc[mi][nt][1] + b1v;
                Pact[(r0+8)*264 + colg]   = acc[mi][nt][2] + b0v;
                Pact[(r0+8)*264 + colg+1] = acc[mi][nt][3] + b1v;
            } else {
                int cc = colg - 256;
                float b0v = beg[cc], b1v = beg[cc+1];
                float s0 = acc[mi][nt][0] + b0v, s1 = acc[mi][nt][1] + b1v;
                float s2 = acc[mi][nt][2] + b0v, s3 = acc[mi][nt][3] + b1v;
                Gact[r0*264 + cc]       = 1.f / (1.f + __expf(-s0));
                Gact[r0*264 + cc + 1]   = 1.f / (1.f + __expf(-s1));
                Gact[(r0+8)*264 + cc]   = 1.f / (1.f + __expf(-s2));
                Gact[(r0+8)*264 + cc+1] = 1.f / (1.f + __expf(-s3));
            }
        }
    __syncthreads();

    // per-head gated reduction: 64 rows x 8 heads = 512 outputs
    {
        int r = tid >> 3, h = tid & 7;
        int base = r*264 + h*32;
        float s = 0.f;
        #pragma unroll
        for (int d = 0; d < 32; d++) {
            int dp = (d + tid) & 31;
            s += Pact[base + dp] * Gact[base + dp];
        }
        size_t i = i0 + r;
        int m = (int)(i & 255), n = (int)((i >> 8) & 255), b = (int)(i >> 16);
        g_eattn[(((size_t)(b*NH + h)*NN + n)*NN) + m] = s;
    }
}

// ---------------- fused attention: scores + bias + mask + softmax + attn@V ----------------
#define AKS 264
#define AVS 36
#define AQS 33
#define ATT_SMEM ((32*AKS + 256*AVS + 32*AQS + 32*AKS) * 4)

__global__ __launch_bounds__(256, 1)
void attention_kernel(const int* __restrict__ adj)
{
    extern __shared__ float smf[];
    float* Kt = smf;
    float* Vs = Kt + 32*AKS;
    float* Qs = Vs + 256*AVS;
    float* Ps = Qs + 32*AQS;

    int bid = blockIdx.x;
    int nb = bid & 7, h = (bid >> 3) & 7, b = bid >> 6;
    int n0 = nb * 32;
    int tid = threadIdx.x;

    const float* kbase = g_k + (size_t)(b*NN)*HIDD + h*DH;
    const float* vbase = g_v + (size_t)(b*NN)*HIDD + h*DH;
    #pragma unroll
    for (int it = 0; it < 32; it++) {
        int idx = tid + it*256;
        int m = idx >> 5, d = idx & 31;
        float kv = kbase[(size_t)m*HIDD + d];
        float vv = vbase[(size_t)m*HIDD + d];
        Kt[d*AKS + m] = kv;
        Vs[m*AVS + d] = vv;
    }
    #pragma unroll
    for (int it = 0; it < 4; it++) {
        int idx = tid + it*256;
        int r = idx >> 5, d = idx & 31;
        Qs[r*AQS + d] = g_q[(size_t)(b*NN + n0 + r)*HIDD + h*DH + d];
    }
    __syncthreads();

    int r = tid >> 3, cg = tid & 7;

    float acc[8][4];
    #pragma unroll
    for (int c = 0; c < 8; c++)
        #pragma unroll
        for (int j = 0; j < 4; j++) acc[c][j] = 0.f;

    #pragma unroll
    for (int d = 0; d < 32; d++) {
        float qd = Qs[r*AQS + d];
        const float* krow = Kt + d*AKS + cg*4;
        #pragma unroll
        for (int c = 0; c < 8; c++) {
            float4 kv = *(const float4*)(krow + c*32);
            acc[c][0] = fmaf(qd, kv.x, acc[c][0]);
            acc[c][1] = fmaf(qd, kv.y, acc[c][1]);
            acc[c][2] = fmaf(qd, kv.z, acc[c][2]);
            acc[c][3] = fmaf(qd, kv.w, acc[c][3]);
        }
    }

    size_t rowbase = ((size_t)(b*NH + h)*NN + (n0 + r)) * NN;
    const float* erow = g_eattn + rowbase;
    const int*   arow = adj + (size_t)(b*NN + n0 + r)*NN;

    const float scale = 0.17677669529663687f;
    float mx = -1e30f;
    #pragma unroll
    for (int c = 0; c < 8; c++) {
        int m0 = cg*4 + c*32;
        float4 ev = *(const float4*)(erow + m0);
        int4   av = *(const int4*)(arow + m0);
        acc[c][0] = (av.x == 0) ? -1e9f : fmaf(acc[c][0], scale, ev.x);
        acc[c][1] = (av.y == 0) ? -1e9f : fmaf(acc[c][1], scale, ev.y);
        acc[c][2] = (av.z == 0) ? -1e9f : fmaf(acc[c][2], scale, ev.z);
        acc[c][3] = (av.w == 0) ? -1e9f : fmaf(acc[c][3], scale, ev.w);
        #pragma unroll
        for (int j = 0; j < 4; j++) mx = fmaxf(mx, acc[c][j]);
    }
    #pragma unroll
    for (int o = 1; o < 8; o <<= 1) mx = fmaxf(mx, __shfl_xor_sync(0xffffffffu, mx, o));

    float sum = 0.f;
    #pragma unroll
    for (int c = 0; c < 8; c++)
        #pragma unroll
        for (int j = 0; j < 4; j++) {
            acc[c][j] = __expf(acc[c][j] - mx);
            sum += acc[c][j];
        }
    #pragma unroll
    for (int o = 1; o < 8; o <<= 1) sum += __shfl_xor_sync(0xffffffffu, sum, o);
    float inv = 1.f / sum;

    float* psrow = Ps + r*AKS;
    float* grow  = g_scores + rowbase;
    #pragma unroll
    for (int c = 0; c < 8; c++) {
        int m0 = cg*4 + c*32;
        float4 p;
        p.x = acc[c][0] * inv; p.y = acc[c][1] * inv;
        p.z = acc[c][2] * inv; p.w = acc[c][3] * inv;
        *(float4*)(psrow + m0) = p;
        *(float4*)(grow + m0)  = p;
    }
    __syncwarp();

    float o0 = 0.f, o1 = 0.f, o2 = 0.f, o3 = 0.f;
    #pragma unroll 8
    for (int m = 0; m < 256; m++) {
        float p = psrow[m];
        float4 vv = *(const float4*)(Vs + m*AVS + cg*4);
        o0 = fmaf(p, vv.x, o0);
        o1 = fmaf(p, vv.y, o1);
        o2 = fmaf(p, vv.z, o2);
        o3 = fmaf(p, vv.w, o3);
    }
    float4 ov = {o0, o1, o2, o3};
    *(float4*)(g_ao + (size_t)(b*NN + n0 + r)*HIDD + h*DH + cg*4) = ov;
}

// ---------------- generic fp32 GEMM body: 32x64 tile, BK=32 ----------------
__device__ __forceinline__ void gemm_body(const float* __restrict__ A, const float* __restrict__ W,
                                          const float* __restrict__ bias, float* __restrict__ C,
                                          int M, int Nc, int K, int bx, int by)
{
    __shared__ float As[32][33];
    __shared__ float Ws[32][64];
    int tid = threadIdx.x;
    int r0 = by * 32, c0 = bx * 64;
    int ty = tid >> 4, tx = tid & 15;
    float acc[2][4] = {};

    for (int kc = 0; kc < K; kc += 32) {
        {
            int r = tid >> 3, c4 = tid & 7;
            float4 v = *(const float4*)(A + (size_t)(r0 + r)*K + kc + c4*4);
            As[c4*4+0][r] = v.x; As[c4*4+1][r] = v.y;
            As[c4*4+2][r] = v.z; As[c4*4+3][r] = v.w;
        }
        #pragma unroll
        for (int it = 0; it < 2; it++) {
            int j = tid + it*256;
            int rr = j >> 4, c4 = j & 15;
            *(float4*)(&Ws[rr][c4*4]) = *(const float4*)(W + (size_t)(kc + rr)*Nc + c0 + c4*4);
        }
        __syncthreads();
        #pragma unroll
        for (int k = 0; k < 32; k++) {
            float a0 = As[k][ty*2], a1 = As[k][ty*2+1];
            float4 bv = *(float4*)(&Ws[k][tx*4]);
            acc[0][0] = fmaf(a0, bv.x, acc[0][0]);
            acc[0][1] = fmaf(a0, bv.y, acc[0][1]);
            acc[0][2] = fmaf(a0, bv.z, acc[0][2]);
            acc[0][3] = fmaf(a0, bv.w, acc[0][3]);
            acc[1][0] = fmaf(a1, bv.x, acc[1][0]);
            acc[1][1] = fmaf(a1, bv.y, acc[1][1]);
            acc[1][2] = fmaf(a1, bv.z, acc[1][2]);
            acc[1][3] = fmaf(a1, bv.w, acc[1][3]);
        }
        __syncthreads();
    }
    #pragma unroll
    for (int i = 0; i < 2; i++)
        #pragma unroll
        for (int j = 0; j < 4; j++) {
            int cc = c0 + tx*4 + j;
            float v = acc[i][j];
            if (bias) v += bias[cc];
            C[(size_t)(r0 + ty*2 + i)*Nc + cc] = v;
        }
}

__global__ __launch_bounds__(256)
void gemm_one_kernel(const float* __restrict__ A, const float* __restrict__ W,
                     const float* __restrict__ bias, float* __restrict__ C,
                     int M, int Nc, int K)
{
    gemm_body(A, W, bias, C, M, Nc, K, blockIdx.x, blockIdx.y);
}

__global__ __launch_bounds__(256)
void gemm_qkv_kernel(const float* __restrict__ A,
                     const float* __restrict__ Wq, const float* __restrict__ bq,
                     const float* __restrict__ Wk, const float* __restrict__ bk,
                     const float* __restrict__ Wv, const float* __restrict__ bv,
                     float* __restrict__ oq, float* __restrict__ ok, float* __restrict__ ov)
{
    int z = blockIdx.z;
    const float* W = (z == 0) ? Wq : (z == 1) ? Wk : Wv;
    const float* bb = (z == 0) ? bq : (z == 1) ? bk : bv;
    float* C = (z == 0) ? oq : (z == 1) ? ok : ov;
    gemm_body(A, W, bb, C, 512, 256, 256, blockIdx.x, blockIdx.y);
}

// ---------------- attn mean over heads ----------------
__global__ __launch_bounds__(256)
void attn_mean_kernel()
{
    int j = blockIdx.x * 256 + threadIdx.x;
    int b = j >> 16, nm = j & 65535;
    float s = 0.f;
    #pragma unroll
    for (int h = 0; h < NH; h++) s += g_scores[(((size_t)(b*NH + h)) << 16) + nm];
    g_amean[j] = s * 0.125f;
}

// ---------------- h_out = LN(residual + o)  (warp per row) ----------------
__global__ __launch_bounds__(256)
void ln_node_kernel(const float* __restrict__ g1, const float* __restrict__ b1,
                    float* __restrict__ out)
{
    int row = blockIdx.x * 8 + (threadIdx.x >> 5);
    int lane = threadIdx.x & 31;
    const float* ha = g_h + (size_t)row*256;
    const float* ta = g_tmp + (size_t)row*256;
    float4 a0 = *(const float4*)(ha + lane*4);
    float4 t0 = *(const float4*)(ta + lane*4);
    float4 a1 = *(const float4*)(ha + 128 + lane*4);
    float4 t1 = *(const float4*)(ta + 128 + lane*4);
    float x[8] = {a0.x+t0.x, a0.y+t0.y, a0.z+t0.z, a0.w+t0.w,
                  a1.x+t1.x, a1.y+t1.y, a1.z+t1.z, a1.w+t1.w};
    float s = 0.f;
    #pragma unroll
    for (int j = 0; j < 8; j++) s += x[j];
    float mean = warpSum(s) * (1.f/256.f);
    float vs = 0.f;
    #pragma unroll
    for (int j = 0; j < 8; j++) { float d = x[j] - mean; vs += d*d; }
    float inv = rsqrtf(warpSum(vs) * (1.f/256.f) + LN_EPS);
    float* o = out + (size_t)row*256;
    #pragma unroll
    for (int j = 0; j < 8; j++) {
        int c = (j < 4) ? (lane*4 + j) : (128 + lane*4 + j - 4);
        o[c] = (x[j] - mean) * inv * g1[c] + b1[c];
    }
}

// ---------------- edge_out = LN(E + amean*0.5*(P_n + P_m) + beo)  (warp per row) ----------------
__global__ __launch_bounds__(256)
void edge_out_kernel(const float* __restrict__ E, const float* __restrict__ beo,
                     const float* __restrict__ g2, const float* __restrict__ b2,
                     float* __restrict__ out)
{
    size_t i = (size_t)blockIdx.x * 8 + (threadIdx.x >> 5);
    int lane = threadIdx.x & 31;
    int m = (int)(i & 255), n = (int)((i >> 8) & 255), b = (int)(i >> 16);
    float am = g_amean[i] * 0.5f;
    const float* Er = E + i*256;
    const float* Pn = g_P + (size_t)(b*NN + n)*256;
    const float* Pm = g_P + (size_t)(b*NN + m)*256;

    float x[8];
    #pragma unroll
    for (int half = 0; half < 2; half++) {
        int c = half*128 + lane*4;
        float4 e  = *(const float4*)(Er + c);
        float4 pn = *(const float4*)(Pn + c);
        float4 pm = *(const float4*)(Pm + c);
        float4 bo = *(const float4*)(beo + c);
        x[half*4+0] = e.x + am*(pn.x + pm.x) + bo.x;
        x[half*4+1] = e.y + am*(pn.y + pm.y) + bo.y;
        x[half*4+2] = e.z + am*(pn.z + pm.z) + bo.z;
        x[half*4+3] = e.w + am*(pn.w + pm.w) + bo.w;
    }
    float s = 0.f;
    #pragma unroll
    for (int j = 0; j < 8; j++) s += x[j];
    float mean = warpSum(s) * (1.f/256.f);
    float vs = 0.f;
    #pragma unroll
    for (int j = 0; j < 8; j++) { float d = x[j] - mean; vs += d*d; }
    float inv = rsqrtf(warpSum(vs) * (1.f/256.f) + LN_EPS);
    float* o = out + i*256;
    #pragma unroll
    for (int half = 0; half < 2; half++) {
        int c = half*128 + lane*4;
        float4 gg = *(const float4*)(g2 + c);
        float4 bb = *(const float4*)(b2 + c);
        float4 r;
        r.x = (x[half*4+0] - mean) * inv * gg.x + bb.x;
        r.y = (x[half*4+1] - mean) * inv * gg.y + bb.y;
        r.z = (x[half*4+2] - mean) * inv * gg.z + bb.z;
        r.w = (x[half*4+3] - mean) * inv * gg.w + bb.w;
        *(float4*)(o + c) = r;
    }
}

// ---------------- launch ----------------
extern "C" void kernel_launch(void* const* d_in, const int* in_sizes, int n_in,
                              void* d_out, int out_size)
{
    const float* node = (const float*)d_in[0];
    const float* edge = (const float*)d_in[1];
    const int*   adj  = (const int*)  d_in[2];
    const float* Wn  = (const float*)d_in[3];  const float* bn  = (const float*)d_in[4];
    const float* Wq  = (const float*)d_in[5];  const float* bq  = (const float*)d_in[6];
    const float* Wk  = (const float*)d_in[7];  const float* bk  = (const float*)d_in[8];
    const float* Wv  = (const float*)d_in[9];  const float* bv  = (const float*)d_in[10];
    const float* Wep = (const float*)d_in[11]; const float* bep = (const float*)d_in[12];
    const float* Weg = (const float*)d_in[13]; const float* beg = (const float*)d_in[14];
    const float* Wo  = (const float*)d_in[15]; const float* bo  = (const float*)d_in[16];
    const float* Weo = (const float*)d_in[17]; const float* beo = (const float*)d_in[18];
    const float* g1  = (const float*)d_in[19]; const float* b1  = (const float*)d_in[20];
    const float* g2  = (const float*)d_in[21]; const float* b2  = (const float*)d_in[22];

    float* out   = (float*)d_out;
    float* h_out = out;
    float* e_out = out + (size_t)BB*NN*HIDD;

    float *ph, *pq, *pk, *pv, *pao, *ptmp, *pP;
    cudaGetSymbolAddress((void**)&ph,   g_h);
    cudaGetSymbolAddress((void**)&pq,   g_q);
    cudaGetSymbolAddress((void**)&pk,   g_k);
    cudaGetSymbolAddress((void**)&pv,   g_v);
    cudaGetSymbolAddress((void**)&pao,  g_ao);
    cudaGetSymbolAddress((void**)&ptmp, g_tmp);
    cudaGetSymbolAddress((void**)&pP,   g_P);

    cudaFuncSetAttribute(edge_attn_mma_kernel,
                         cudaFuncAttributeMaxDynamicSharedMemorySize, EDGE_SMEM);
    cudaFuncSetAttribute(attention_kernel,
                         cudaFuncAttributeMaxDynamicSharedMemorySize, ATT_SMEM);

    // weight convert/permute (independent) + node projection
    cvt_w_kernel<<<256, 256>>>(Wep, Weg);
    gemm_one_kernel<<<dim3(4, 16), 256>>>(node, Wn, bn, ph, 512, 256, 128);

    // QKV in one launch
    gemm_qkv_kernel<<<dim3(4, 16, 3), 256>>>(ph, Wq, bq, Wk, bk, Wv, bv, pq, pk, pv);

    // edge bias (tensor cores), then fused attention
    edge_attn_mma_kernel<<<(BB*NN*NN)/64, 512, EDGE_SMEM>>>(edge, bep, beg);
    attention_kernel<<<BB*NH*8, 256, ATT_SMEM>>>(adj);

    // mean over heads (for edge update)
    attn_mean_kernel<<<(BB*NN*NN)/256, 256>>>();

    // out-proj + node LN
    gemm_one_kernel<<<dim3(4, 16), 256>>>(pao, Wo, bo, ptmp, 512, 256, 256);
    ln_node_kernel<<<(BB*NN)/8, 256>>>(g1, b1, h_out);

    // P = h_out @ Weo, then fused edge output LN
    gemm_one_kernel<<<dim3(4, 16), 256>>>(h_out, Weo, (const float*)nullptr, pP, 512, 256, 256);
    edge_out_kernel<<<(BB*NN*NN)/8, 256>>>(edge, beo, g2, b2, e_out);
}